// round 3
// baseline (speedup 1.0000x reference)
#include <cuda_runtime.h>
#include <math.h>

#define B_ 4
#define T_ 4096
#define D_ 1024
#define H_ 16
#define C_ 64
#define N_ 64
#define BT_ (B_*T_)
#define BHN_ (B_*H_*N_)

// ---------- scratch (device globals; allocation is forbidden) ----------
__device__ float g_v[BT_*D_];        // x @ w_write
__device__ float g_og[BT_*D_];       // gated attention output, (B,T,D)
__device__ float g_gate[BT_*H_];
__device__ float g_beta[BT_*H_];
__device__ float g_dec[BT_*H_];
__device__ float g_rkd[BHN_*4096];   // rk * dexp
__device__ float g_wkcd[BHN_*4096];  // A @ (wk*beta*dexp)
__device__ float g_vc[BHN_*4096];    // A @ (v*beta)
__device__ float g_wkdw[BHN_*4096];  // wk * exp(last-cum)
__device__ float g_intra[BHN_*4096]; // (rk@wk^T)*L
__device__ float g_elast[BHN_];

// ---------------- small projections ----------------
__global__ __launch_bounds__(256) void proj_kernel(
    const float* __restrict__ x, const float* __restrict__ wg,
    const float* __restrict__ wb, const float* __restrict__ wa,
    const float* __restrict__ dtb, const float* __restrict__ alog)
{
    __shared__ float xr[D_];
    int row = blockIdx.x;
    int t = threadIdx.x;
    *(float4*)&xr[t*4] = *(const float4*)&x[(size_t)row*D_ + t*4];
    __syncthreads();
    int w = t >> 5, lane = t & 31;
    for (int o = w*6; o < w*6+6 && o < 48; o++) {
        int which = o >> 4, h = o & 15;
        const float* W = (which==0) ? wg : ((which==1) ? wb : wa);
        float s = 0.f;
        for (int j = lane; j < D_; j += 32) s += xr[j]*W[j*H_ + h];
        #pragma unroll
        for (int off=16; off>0; off>>=1) s += __shfl_down_sync(0xffffffffu, s, off);
        if (lane==0) {
            int idx = row*H_ + h;
            if (which==0)      g_gate[idx] = 1.f/(1.f+expf(-s));
            else if (which==1) g_beta[idx] = 1.f/(1.f+expf(-s));
            else {
                float v = s + dtb[h];
                float sp = fmaxf(v, 0.f) + log1pf(expf(-fabsf(v)));
                g_dec[idx] = -expf(alog[h])*sp;
            }
        }
    }
}

// ---------------- SGEMM 128x128 tile, 256 thr, 8x8/thread ----------------
// mode 0: g_v  = Ain  @ Bw
// mode 1: Cout = R + g_og @ Bw
__global__ __launch_bounds__(256) void sgemm_nn(
    const float* Ain, const float* __restrict__ Bw,
    const float* __restrict__ R, float* Cout, int mode)
{
    const int Nn = 1024, K = 1024;
    __shared__ float As[16][128];
    __shared__ float Bs[16][128];
    const float* A = mode ? (const float*)g_og : Ain;
    float* C = mode ? Cout : (float*)g_v;

    int t = threadIdx.x;
    int bm = blockIdx.y, bn = blockIdx.x;
    int ty = t >> 4, tx = t & 15;
    int aRow = t >> 2, aCol = (t & 3) << 2;
    int bRow = t >> 5, bCol = (t & 31) << 2;
    const float* Ab = A + (size_t)(bm*128)*K;
    const float* Bp = Bw + bn*128;

    float acc[8][8];
    #pragma unroll
    for (int i=0;i<8;i++)
        #pragma unroll
        for (int j=0;j<8;j++) acc[i][j]=0.f;

    for (int kt = 0; kt < K; kt += 16) {
        float4 a0 = *(const float4*)&Ab[(size_t)aRow*K + kt + aCol];
        float4 a1 = *(const float4*)&Ab[(size_t)(aRow+64)*K + kt + aCol];
        float4 b0 = *(const float4*)&Bp[(size_t)(kt+bRow)*Nn + bCol];
        float4 b1 = *(const float4*)&Bp[(size_t)(kt+bRow+8)*Nn + bCol];
        __syncthreads();
        As[aCol+0][aRow]    = a0.x; As[aCol+1][aRow]    = a0.y;
        As[aCol+2][aRow]    = a0.z; As[aCol+3][aRow]    = a0.w;
        As[aCol+0][aRow+64] = a1.x; As[aCol+1][aRow+64] = a1.y;
        As[aCol+2][aRow+64] = a1.z; As[aCol+3][aRow+64] = a1.w;
        *(float4*)&Bs[bRow][bCol]   = b0;
        *(float4*)&Bs[bRow+8][bCol] = b1;
        __syncthreads();
        #pragma unroll
        for (int k=0;k<16;k++) {
            float av[8], bv[8];
            *(float4*)(av)   = *(const float4*)&As[k][ty*8];
            *(float4*)(av+4) = *(const float4*)&As[k][ty*8+4];
            *(float4*)(bv)   = *(const float4*)&Bs[k][tx*8];
            *(float4*)(bv+4) = *(const float4*)&Bs[k][tx*8+4];
            #pragma unroll
            for (int i=0;i<8;i++)
                #pragma unroll
                for (int j=0;j<8;j++) acc[i][j] += av[i]*bv[j];
        }
    }
    int row0 = bm*128 + ty*8;
    int col0 = bn*128 + tx*8;
    #pragma unroll
    for (int i=0;i<8;i++) {
        size_t off = (size_t)(row0+i)*Nn + col0;
        float4 v0 = make_float4(acc[i][0],acc[i][1],acc[i][2],acc[i][3]);
        float4 v1 = make_float4(acc[i][4],acc[i][5],acc[i][6],acc[i][7]);
        if (mode) {
            float4 r0 = *(const float4*)&R[off];
            float4 r1 = *(const float4*)&R[off+4];
            v0.x+=r0.x; v0.y+=r0.y; v0.z+=r0.z; v0.w+=r0.w;
            v1.x+=r1.x; v1.y+=r1.y; v1.z+=r1.z; v1.w+=r1.w;
        }
        *(float4*)&C[off]   = v0;
        *(float4*)&C[off+4] = v1;
    }
}

// ---------------- per-chunk preparation ----------------
#define RKS 65
#define PREP_SMEM ((64*RKS + 64*64 + 64*64 + 64*4 + 8)*4)

__global__ __launch_bounds__(256) void prep_kernel(const float* __restrict__ x)
{
    extern __shared__ float sm[];
    float* RK    = sm;            // 64*65  normalized rk rows (this chunk)
    float* Mb    = RK + 64*RKS;   // 64*64  Bm, later VS=v*beta
    float* Am    = Mb + 64*64;    // 64*64  A
    float* cum   = Am + 64*64;    // 64
    float* dexpv = cum + 64;      // 64
    float* betav = dexpv + 64;    // 64
    float* w0    = betav + 64;    // 64  wk row for c=0
    float* extra = w0 + 64;       // 8

    int cid = blockIdx.x;
    int b = cid / (H_*N_);
    int h = (cid / N_) % H_;
    int n = cid % N_;
    int t = threadIdx.x;
    int lj = t & 63;
    int g  = t >> 6;
    size_t xbase = ((size_t)b*T_ + (size_t)n*C_)*D_ + (size_t)h*64;
    size_t base  = (size_t)cid*4096;

    // loads
    for (int idx=t; idx<4096; idx+=256) {
        int c = idx>>6, j = idx&63;
        RK[c*RKS + j] = x[xbase + (size_t)c*D_ + j];
    }
    if (t < 64) {
        int tok = (b*T_ + n*C_ + t)*H_ + h;
        betav[t] = g_beta[tok];
        cum[t]   = g_dec[tok];
    }
    if (t >= 64 && t < 128) {
        int j = t - 64;
        w0[j] = (n > 0) ? x[xbase - D_ + j] : 0.f;
    }
    __syncthreads();

    // normalize, cumsum
    if (t < 64) {
        float s = 0.f;
        for (int j=0;j<64;j++){ float v = RK[t*RKS+j]; s += v*v; }
        float inv = 1.f/fmaxf(sqrtf(s), 1e-12f);
        for (int j=0;j<64;j++) RK[t*RKS+j] *= inv;
    }
    if (t == 64) {
        float s = 0.f;
        for (int j=0;j<64;j++) s += w0[j]*w0[j];
        extra[0] = 1.f/fmaxf(sqrtf(s), 1e-12f);
    }
    if (t == 65) {
        float s = 0.f;
        for (int c=0;c<64;c++){ s += cum[c]; cum[c] = s; }
    }
    __syncthreads();
    if (t < 64) {
        w0[t] *= extra[0];
        dexpv[t] = expf(cum[t]);
    }
    __syncthreads();

    // Bm[i][j] = -beta[i]*L[i][j]*dot(wk_i,wk_j), j<i
    {
        const float* rowPtr[16];
        #pragma unroll
        for (int ii=0; ii<16; ii++) {
            int i = g + 4*ii;
            rowPtr[ii] = (i==0) ? w0 : &RK[(i-1)*RKS];
        }
        const float* rowk = (lj==0) ? w0 : &RK[(lj-1)*RKS];
        float acc[16];
        #pragma unroll
        for (int ii=0; ii<16; ii++) acc[ii]=0.f;
        for (int m=0;m<64;m++){
            float wkm = rowk[m];
            #pragma unroll
            for (int ii=0; ii<16; ii++) acc[ii] += rowPtr[ii][m]*wkm;
        }
        #pragma unroll
        for (int ii=0; ii<16; ii++){
            int i = g + 4*ii;
            Mb[i*64 + lj] = (lj < i) ? (-betav[i]*expf(cum[i]-cum[lj])*acc[ii]) : 0.f;
        }
    }
    __syncthreads();

    // A = (I - Bm)^{-1} forward substitution (unit lower)
    for (int idx=t; idx<4096; idx+=256)
        Am[idx] = ((idx>>6)==(idx&63)) ? 1.f : 0.f;
    __syncthreads();
    for (int k=0;k<63;k++){
        for (int i=k+1+g; i<64; i+=4)
            Am[i*64+lj] += Mb[i*64+k]*Am[k*64+lj];
        __syncthreads();
    }

    // intra = (rk@wk^T)*L ; rkd ; wkdw ; elast
    {
        const float* rowPtr[16];
        #pragma unroll
        for (int ii=0; ii<16; ii++) rowPtr[ii] = &RK[(g+4*ii)*RKS];
        const float* rowj = (lj==0) ? w0 : &RK[(lj-1)*RKS];
        float acc[16];
        #pragma unroll
        for (int ii=0; ii<16; ii++) acc[ii]=0.f;
        for (int m=0;m<64;m++){
            float wjm = rowj[m];
            #pragma unroll
            for (int ii=0; ii<16; ii++) acc[ii] += rowPtr[ii][m]*wjm;
        }
        #pragma unroll
        for (int ii=0; ii<16; ii++){
            int i = g + 4*ii;
            g_intra[base + i*64 + lj] = (i >= lj) ? (expf(cum[i]-cum[lj])*acc[ii]) : 0.f;
        }
    }
    float cum63 = cum[63];
    for (int idx=t; idx<4096; idx+=256){
        int c = idx>>6, j = idx&63;
        g_rkd[base+idx] = RK[c*RKS+j]*dexpv[c];
        float wcj = (c==0) ? w0[j] : RK[(c-1)*RKS+j];
        g_wkdw[base+idx] = wcj*expf(cum63 - cum[c]);
    }
    if (t==0) g_elast[cid] = expf(cum63);

    // VS = v*beta (reuse Mb)
    for (int idx=t; idx<4096; idx+=256){
        int c = idx>>6, j = idx&63;
        Mb[c*64+j] = g_v[xbase + (size_t)c*D_ + j]*betav[c];
    }
    __syncthreads();

    // vcorr = A@VS ; wkcd = A@(wk*beta*dexp)
    {
        float accv[16], accw[16];
        #pragma unroll
        for (int ii=0; ii<16; ii++){ accv[ii]=0.f; accw[ii]=0.f; }
        for (int k=0;k<64;k++){
            float vs = Mb[k*64 + lj];
            float wkv = ((k==0) ? w0[lj] : RK[(k-1)*RKS+lj]) * betav[k]*dexpv[k];
            #pragma unroll
            for (int ii=0; ii<16; ii++){
                float a = Am[(g+4*ii)*64 + k];
                accv[ii] += a*vs;
                accw[ii] += a*wkv;
            }
        }
        #pragma unroll
        for (int ii=0; ii<16; ii++){
            int i = g + 4*ii;
            g_vc[base + i*64 + lj]   = accv[ii];
            g_wkcd[base + i*64 + lj] = accw[ii];
        }
    }
}

// ---------------- sequential inter-chunk scan ----------------
#define SCAN_SMEM ((7*4096 + 64 + 16)*4)

__global__ __launch_bounds__(256) void scan_kernel()
{
    extern __shared__ float sm[];
    float* S     = sm;            // state 64x64 [k][e]
    float* VN    = S + 4096;      // v_new
    float* VC    = VN + 4096;
    float* WKCD  = VC + 4096;
    float* RKD   = WKCD + 4096;
    float* INTRA = RKD + 4096;
    float* WKDW  = INTRA + 4096;
    float* gatev = WKDW + 4096;   // 64
    float* misc  = gatev + 64;    // [0..7] warp partials, [8] elast, [9] factor

    int bh = blockIdx.x;
    int b = bh >> 4, h = bh & 15;
    int t = threadIdx.x;
    int lane = t & 31, w = t >> 5;
    int ebl = (t & 15) * 4;
    int cbl = (t >> 4) * 4;

    for (int idx=t; idx<4096; idx+=256) S[idx]=0.f;
    __syncthreads();

    for (int n=0; n<64; n++){
        // load chunk tiles
        size_t gb = ((size_t)bh*64 + n)*4096;
        for (int i=t; i<1024; i+=256) {
            ((float4*)VC)[i]    = ((const float4*)(g_vc+gb))[i];
            ((float4*)WKCD)[i]  = ((const float4*)(g_wkcd+gb))[i];
            ((float4*)RKD)[i]   = ((const float4*)(g_rkd+gb))[i];
            ((float4*)INTRA)[i] = ((const float4*)(g_intra+gb))[i];
            ((float4*)WKDW)[i]  = ((const float4*)(g_wkdw+gb))[i];
        }
        if (t < 64) gatev[t] = g_gate[((size_t)b*T_ + n*64 + t)*H_ + h];
        if (t == 0) misc[8] = g_elast[bh*64 + n];
        __syncthreads();

        // v_new = vc - wkcd @ S
        {
            float acc[4][4];
            #pragma unroll
            for (int ci=0;ci<4;ci++){
                float4 v = *(float4*)&VC[(cbl+ci)*64 + ebl];
                acc[ci][0]=v.x; acc[ci][1]=v.y; acc[ci][2]=v.z; acc[ci][3]=v.w;
            }
            #pragma unroll 8
            for (int k=0;k<64;k++){
                float4 s = *(float4*)&S[k*64 + ebl];
                #pragma unroll
                for (int ci=0;ci<4;ci++){
                    float wv = WKCD[(cbl+ci)*64 + k];
                    acc[ci][0] -= wv*s.x; acc[ci][1] -= wv*s.y;
                    acc[ci][2] -= wv*s.z; acc[ci][3] -= wv*s.w;
                }
            }
            #pragma unroll
            for (int ci=0;ci<4;ci++)
                *(float4*)&VN[(cbl+ci)*64 + ebl] =
                    make_float4(acc[ci][0],acc[ci][1],acc[ci][2],acc[ci][3]);
        }
        __syncthreads();

        // o = rkd@S + intra@v_new ; upd = wkdw^T @ v_new
        float upd[4][4];
        {
            float oa[4][4];
            #pragma unroll
            for (int ci=0;ci<4;ci++)
                #pragma unroll
                for (int ei=0;ei<4;ei++){ oa[ci][ei]=0.f; upd[ci][ei]=0.f; }
            #pragma unroll 8
            for (int k=0;k<64;k++){
                float4 s = *(float4*)&S[k*64 + ebl];
                #pragma unroll
                for (int ci=0;ci<4;ci++){
                    float wv = RKD[(cbl+ci)*64 + k];
                    oa[ci][0] += wv*s.x; oa[ci][1] += wv*s.y;
                    oa[ci][2] += wv*s.z; oa[ci][3] += wv*s.w;
                }
            }
            #pragma unroll 8
            for (int k=0;k<64;k++){
                float4 v = *(float4*)&VN[k*64 + ebl];
                #pragma unroll
                for (int ci=0;ci<4;ci++){
                    float wv = INTRA[(cbl+ci)*64 + k];
                    oa[ci][0] += wv*v.x; oa[ci][1] += wv*v.y;
                    oa[ci][2] += wv*v.z; oa[ci][3] += wv*v.w;
                }
                #pragma unroll
                for (int di=0;di<4;di++){
                    float wd = WKDW[k*64 + cbl + di];
                    upd[di][0] += wd*v.x; upd[di][1] += wd*v.y;
                    upd[di][2] += wd*v.z; upd[di][3] += wd*v.w;
                }
            }
            #pragma unroll
            for (int ci=0;ci<4;ci++){
                float gt = gatev[cbl+ci];
                size_t orow = ((size_t)b*T_ + n*64 + cbl+ci)*D_ + (size_t)h*64 + ebl;
                *(float4*)&g_og[orow] = make_float4(oa[ci][0]*gt, oa[ci][1]*gt,
                                                    oa[ci][2]*gt, oa[ci][3]*gt);
            }
        }
        __syncthreads();

        // S = S*elast + upd ; Frobenius norm
        float el = misc[8];
        float partial = 0.f;
        #pragma unroll
        for (int di=0;di<4;di++){
            #pragma unroll
            for (int ei=0;ei<4;ei++){
                int idx = (cbl+di)*64 + ebl + ei;
                float sv = S[idx]*el + upd[di][ei];
                S[idx] = sv;
                partial += sv*sv;
            }
        }
        #pragma unroll
        for (int off=16; off>0; off>>=1) partial += __shfl_down_sync(0xffffffffu, partial, off);
        if (lane==0) misc[w] = partial;
        __syncthreads();
        if (t==0){
            float s=0.f;
            #pragma unroll
            for (int i=0;i<8;i++) s += misc[i];
            float nrm = sqrtf(s);
            misc[9] = fminf(nrm,100.f)/fmaxf(nrm,1e-6f);
        }
        __syncthreads();
        float f = misc[9];
        #pragma unroll
        for (int di=0;di<4;di++)
            #pragma unroll
            for (int ei=0;ei<4;ei++)
                S[(cbl+di)*64 + ebl + ei] *= f;
        __syncthreads();
    }
}

extern "C" void kernel_launch(void* const* d_in, const int* in_sizes, int n_in,
                              void* d_out, int out_size) {
    const float* x      = (const float*)d_in[0];  // out (residual input)
    const float* w_wr   = (const float*)d_in[1];
    const float* w_gate = (const float*)d_in[2];
    const float* w_out  = (const float*)d_in[3];
    const float* w_beta = (const float*)d_in[4];
    const float* w_alph = (const float*)d_in[5];
    const float* dtb    = (const float*)d_in[6];
    const float* alog   = (const float*)d_in[7];
    float* out = (float*)d_out;

    cudaFuncSetAttribute(prep_kernel, cudaFuncAttributeMaxDynamicSharedMemorySize, PREP_SMEM);
    cudaFuncSetAttribute(scan_kernel, cudaFuncAttributeMaxDynamicSharedMemorySize, SCAN_SMEM);

    proj_kernel<<<BT_, 256>>>(x, w_gate, w_beta, w_alph, dtb, alog);
    sgemm_nn<<<dim3(8,128), 256>>>(x, w_wr, nullptr, nullptr, 0);
    prep_kernel<<<BHN_, 256, PREP_SMEM>>>(x);
    scan_kernel<<<64, 256, SCAN_SMEM>>>();
    sgemm_nn<<<dim3(8,128), 256>>>(nullptr, w_out, x, out, 1);
}

// round 4
// speedup vs baseline: 1.0935x; 1.0935x over previous
#include <cuda_runtime.h>
#include <math.h>

#define B_ 4
#define T_ 4096
#define D_ 1024
#define H_ 16
#define C_ 64
#define N_ 64
#define BT_ (B_*T_)
#define BHN_ (B_*H_*N_)

// ---------- scratch (device globals; allocation is forbidden) ----------
__device__ float g_v[BT_*D_];        // x @ w_write
__device__ float g_og[BT_*D_];       // gated attention output, (B,T,D)
__device__ float g_gate[BT_*H_];
__device__ float g_beta[BT_*H_];
__device__ float g_dec[BT_*H_];
__device__ float g_rkd[BHN_*4096];   // rk * dexp
__device__ float g_wkcd[BHN_*4096];  // A @ (wk*beta*dexp)
__device__ float g_vc[BHN_*4096];    // A @ (v*beta)
__device__ float g_wkdw[BHN_*4096];  // wk * exp(last-cum)
__device__ float g_intra[BHN_*4096]; // (rk@wk^T)*L
__device__ float g_elast[BHN_];

// ---------------- small projections ----------------
__global__ __launch_bounds__(256) void proj_kernel(
    const float* __restrict__ x, const float* __restrict__ wg,
    const float* __restrict__ wb, const float* __restrict__ wa,
    const float* __restrict__ dtb, const float* __restrict__ alog)
{
    __shared__ float xr[D_];
    int row = blockIdx.x;
    int t = threadIdx.x;
    *(float4*)&xr[t*4] = *(const float4*)&x[(size_t)row*D_ + t*4];
    __syncthreads();
    int w = t >> 5, lane = t & 31;
    for (int o = w*6; o < w*6+6 && o < 48; o++) {
        int which = o >> 4, h = o & 15;
        const float* W = (which==0) ? wg : ((which==1) ? wb : wa);
        float s = 0.f;
        for (int j = lane; j < D_; j += 32) s += xr[j]*W[j*H_ + h];
        #pragma unroll
        for (int off=16; off>0; off>>=1) s += __shfl_down_sync(0xffffffffu, s, off);
        if (lane==0) {
            int idx = row*H_ + h;
            if (which==0)      g_gate[idx] = 1.f/(1.f+expf(-s));
            else if (which==1) g_beta[idx] = 1.f/(1.f+expf(-s));
            else {
                float v = s + dtb[h];
                float sp = fmaxf(v, 0.f) + log1pf(expf(-fabsf(v)));
                g_dec[idx] = -expf(alog[h])*sp;
            }
        }
    }
}

// ---------------- TF32 tensor-core GEMM ----------------
// C(M=16384,N=1024) = A @ B  (+ R in mode 1)
// 128x128 tile, BK=32, 256 threads (8 warps as 4x2), m16n8k8 tf32 mma.
// Smem holds operands in FRAGMENT-ORDER so all fetches are LDS.128.
__device__ __forceinline__ unsigned f2tf(float f){
    unsigned u; asm("cvt.rna.tf32.f32 %0, %1;" : "=r"(u) : "f"(f)); return u;
}
__device__ __forceinline__ void mma_tf32(float* c, const unsigned* a,
                                         unsigned b0, unsigned b1){
    asm volatile(
      "mma.sync.aligned.m16n8k8.row.col.f32.tf32.tf32.f32 "
      "{%0,%1,%2,%3}, {%4,%5,%6,%7}, {%8,%9}, {%0,%1,%2,%3};"
      : "+f"(c[0]), "+f"(c[1]), "+f"(c[2]), "+f"(c[3])
      : "r"(a[0]), "r"(a[1]), "r"(a[2]), "r"(a[3]), "r"(b0), "r"(b1));
}

#define GEMM_SMEM (65536)

__global__ __launch_bounds__(256, 1) void tgemm_nn(
    const float* Ain, const float* __restrict__ Bw,
    const float* __restrict__ R, float* Cout, int mode)
{
    const int Nn = 1024, K = 1024;
    extern __shared__ float sm[];
    // layout: A stage0 [0,4096), A stage1 [4096,8192), B stage0 [8192,12288), B stage1 [12288,16384)
    const float* A = mode ? (const float*)g_og : Ain;
    float* C = mode ? Cout : (float*)g_v;

    int t = threadIdx.x;
    int lane = t & 31, warp = t >> 5;
    int wm = warp >> 1, wn = warp & 1;
    int bm = blockIdx.y, bn = blockIdx.x;

    // ---- precompute staging decode (invariant across k-iters) ----
    int aOffs[4], bOffs[4];                 // smem float offsets (within stage)
    const float* aPtr[4]; const float* bPtr[4];
    #pragma unroll
    for (int u=0; u<4; u++){
        int q = t + u*256;                  // float4 id within 128x32 A tile
        int row = q >> 3, cq = (q & 7) * 4;
        int ks = cq >> 3, cloc = cq & 7;
        int mt = row >> 4, rloc = row & 15;
        int g  = rloc & 7;
        int r  = ((cloc >= 4) ? 2 : 0) + ((rloc >= 8) ? 1 : 0);
        aOffs[u] = ((ks*8 + mt)*32 + g*4)*4 + r;          // + i*4 per element
        aPtr[u]  = A + (size_t)(bm*128 + row)*K + cq;

        int kr = q >> 5, nq = (q & 31) * 4; // B tile 32x128
        int ks2 = kr >> 3, tgk = kr & 7;
        int tg2 = tgk & 3, bidx = tgk >> 2;
        int nt = nq >> 3, g0 = nq & 7;
        int ntp = nt >> 1, slot = (nt & 1)*2 + bidx;
        bOffs[u] = ((ks2*8 + ntp)*32 + g0*4 + tg2)*4 + slot;  // + i*16 per element
        bPtr[u]  = Bw + (size_t)kr*Nn + bn*128 + nq;
    }

    float acc[2][8][4];
    #pragma unroll
    for (int mt=0;mt<2;mt++)
        #pragma unroll
        for (int j=0;j<8;j++)
            #pragma unroll
            for (int r=0;r<4;r++) acc[mt][j][r]=0.f;

    float4 aReg[4], bReg[4];
    // preload iter 0
    #pragma unroll
    for (int u=0;u<4;u++){ aReg[u] = *(const float4*)aPtr[u]; bReg[u] = *(const float4*)bPtr[u]; }
    // store stage 0
    #pragma unroll
    for (int u=0;u<4;u++){
        float* As = sm;            float* Bs = sm + 8192;
        const float* av = (const float*)&aReg[u];
        const float* bv = (const float*)&bReg[u];
        #pragma unroll
        for (int i=0;i<4;i++){
            ((unsigned*)As)[aOffs[u] + i*4]  = f2tf(av[i]);
            ((unsigned*)Bs)[bOffs[u] + i*16] = f2tf(bv[i]);
        }
    }
    __syncthreads();

    const int NIT = K/32;
    for (int it=0; it<NIT; it++){
        int cur = it & 1;
        if (it+1 < NIT){
            #pragma unroll
            for (int u=0;u<4;u++){
                aReg[u] = *(const float4*)(aPtr[u] + (it+1)*32);
                bReg[u] = *(const float4*)(bPtr[u] + (size_t)(it+1)*32*Nn);
            }
        }
        // compute on stage cur
        {
            const unsigned* As = (const unsigned*)(sm + cur*4096);
            const unsigned* Bs = (const unsigned*)(sm + 8192 + cur*4096);
            #pragma unroll
            for (int ks=0; ks<4; ks++){
                unsigned af[2][4];
                #pragma unroll
                for (int mt=0;mt<2;mt++){
                    uint4 v = *(const uint4*)&As[((ks*8 + wm*2 + mt)*32 + lane)*4];
                    af[mt][0]=v.x; af[mt][1]=v.y; af[mt][2]=v.z; af[mt][3]=v.w;
                }
                #pragma unroll
                for (int jp=0; jp<4; jp++){
                    uint4 bv = *(const uint4*)&Bs[((ks*8 + wn*4 + jp)*32 + lane)*4];
                    #pragma unroll
                    for (int mt=0;mt<2;mt++){
                        mma_tf32(acc[mt][2*jp],   af[mt], bv.x, bv.y);
                        mma_tf32(acc[mt][2*jp+1], af[mt], bv.z, bv.w);
                    }
                }
            }
        }
        if (it+1 < NIT){
            int nxt = cur ^ 1;
            float* As = sm + nxt*4096;
            float* Bs = sm + 8192 + nxt*4096;
            #pragma unroll
            for (int u=0;u<4;u++){
                const float* av = (const float*)&aReg[u];
                const float* bv = (const float*)&bReg[u];
                #pragma unroll
                for (int i=0;i<4;i++){
                    ((unsigned*)As)[aOffs[u] + i*4]  = f2tf(av[i]);
                    ((unsigned*)Bs)[bOffs[u] + i*16] = f2tf(bv[i]);
                }
            }
        }
        __syncthreads();
    }

    // epilogue
    int g = lane >> 2, tg = lane & 3;
    #pragma unroll
    for (int mt=0; mt<2; mt++){
        int r0 = bm*128 + wm*32 + mt*16 + g;
        #pragma unroll
        for (int j=0; j<8; j++){
            int col = bn*128 + wn*64 + j*8 + tg*2;
            size_t o0 = (size_t)r0*Nn + col;
            size_t o1 = (size_t)(r0+8)*Nn + col;
            float2 v0 = make_float2(acc[mt][j][0], acc[mt][j][1]);
            float2 v1 = make_float2(acc[mt][j][2], acc[mt][j][3]);
            if (mode){
                float2 q0 = *(const float2*)&R[o0];
                float2 q1 = *(const float2*)&R[o1];
                v0.x += q0.x; v0.y += q0.y; v1.x += q1.x; v1.y += q1.y;
            }
            *(float2*)&C[o0] = v0;
            *(float2*)&C[o1] = v1;
        }
    }
}

// ---------------- per-chunk preparation ----------------
#define RKS 65
#define PREP_SMEM ((64*RKS + 64*64 + 64*64 + 64*4 + 8)*4)

__global__ __launch_bounds__(256) void prep_kernel(const float* __restrict__ x)
{
    extern __shared__ float sm[];
    float* RK    = sm;            // 64*65  normalized rk rows (this chunk)
    float* Mb    = RK + 64*RKS;   // 64*64  Bm, later VS=v*beta
    float* Am    = Mb + 64*64;    // 64*64  A
    float* cum   = Am + 64*64;    // 64
    float* dexpv = cum + 64;      // 64
    float* betav = dexpv + 64;    // 64
    float* w0    = betav + 64;    // 64  wk row for c=0
    float* extra = w0 + 64;       // 8

    int cid = blockIdx.x;
    int b = cid / (H_*N_);
    int h = (cid / N_) % H_;
    int n = cid % N_;
    int t = threadIdx.x;
    int lj = t & 63;
    int g  = t >> 6;
    size_t xbase = ((size_t)b*T_ + (size_t)n*C_)*D_ + (size_t)h*64;
    size_t base  = (size_t)cid*4096;

    for (int idx=t; idx<4096; idx+=256) {
        int c = idx>>6, j = idx&63;
        RK[c*RKS + j] = x[xbase + (size_t)c*D_ + j];
    }
    if (t < 64) {
        int tok = (b*T_ + n*C_ + t)*H_ + h;
        betav[t] = g_beta[tok];
        cum[t]   = g_dec[tok];
    }
    if (t >= 64 && t < 128) {
        int j = t - 64;
        w0[j] = (n > 0) ? x[xbase - D_ + j] : 0.f;
    }
    __syncthreads();

    if (t < 64) {
        float s = 0.f;
        for (int j=0;j<64;j++){ float v = RK[t*RKS+j]; s += v*v; }
        float inv = 1.f/fmaxf(sqrtf(s), 1e-12f);
        for (int j=0;j<64;j++) RK[t*RKS+j] *= inv;
    }
    if (t == 64) {
        float s = 0.f;
        for (int j=0;j<64;j++) s += w0[j]*w0[j];
        extra[0] = 1.f/fmaxf(sqrtf(s), 1e-12f);
    }
    if (t == 65) {
        float s = 0.f;
        for (int c=0;c<64;c++){ s += cum[c]; cum[c] = s; }
    }
    __syncthreads();
    if (t < 64) {
        w0[t] *= extra[0];
        dexpv[t] = expf(cum[t]);
    }
    __syncthreads();

    // Bm[i][j] = -beta[i]*L[i][j]*dot(wk_i,wk_j), j<i
    {
        const float* rowPtr[16];
        #pragma unroll
        for (int ii=0; ii<16; ii++) {
            int i = g + 4*ii;
            rowPtr[ii] = (i==0) ? w0 : &RK[(i-1)*RKS];
        }
        const float* rowk = (lj==0) ? w0 : &RK[(lj-1)*RKS];
        float acc[16];
        #pragma unroll
        for (int ii=0; ii<16; ii++) acc[ii]=0.f;
        for (int m=0;m<64;m++){
            float wkm = rowk[m];
            #pragma unroll
            for (int ii=0; ii<16; ii++) acc[ii] += rowPtr[ii][m]*wkm;
        }
        #pragma unroll
        for (int ii=0; ii<16; ii++){
            int i = g + 4*ii;
            Mb[i*64 + lj] = (lj < i) ? (-betav[i]*expf(cum[i]-cum[lj])*acc[ii]) : 0.f;
        }
    }
    __syncthreads();

    for (int idx=t; idx<4096; idx+=256)
        Am[idx] = ((idx>>6)==(idx&63)) ? 1.f : 0.f;
    __syncthreads();
    for (int k=0;k<63;k++){
        for (int i=k+1+g; i<64; i+=4)
            Am[i*64+lj] += Mb[i*64+k]*Am[k*64+lj];
        __syncthreads();
    }

    {
        const float* rowPtr[16];
        #pragma unroll
        for (int ii=0; ii<16; ii++) rowPtr[ii] = &RK[(g+4*ii)*RKS];
        const float* rowj = (lj==0) ? w0 : &RK[(lj-1)*RKS];
        float acc[16];
        #pragma unroll
        for (int ii=0; ii<16; ii++) acc[ii]=0.f;
        for (int m=0;m<64;m++){
            float wjm = rowj[m];
            #pragma unroll
            for (int ii=0; ii<16; ii++) acc[ii] += rowPtr[ii][m]*wjm;
        }
        #pragma unroll
        for (int ii=0; ii<16; ii++){
            int i = g + 4*ii;
            g_intra[base + i*64 + lj] = (i >= lj) ? (expf(cum[i]-cum[lj])*acc[ii]) : 0.f;
        }
    }
    float cum63 = cum[63];
    for (int idx=t; idx<4096; idx+=256){
        int c = idx>>6, j = idx&63;
        g_rkd[base+idx] = RK[c*RKS+j]*dexpv[c];
        float wcj = (c==0) ? w0[j] : RK[(c-1)*RKS+j];
        g_wkdw[base+idx] = wcj*expf(cum63 - cum[c]);
    }
    if (t==0) g_elast[cid] = expf(cum63);

    for (int idx=t; idx<4096; idx+=256){
        int c = idx>>6, j = idx&63;
        Mb[c*64+j] = g_v[xbase + (size_t)c*D_ + j]*betav[c];
    }
    __syncthreads();

    {
        float accv[16], accw[16];
        #pragma unroll
        for (int ii=0; ii<16; ii++){ accv[ii]=0.f; accw[ii]=0.f; }
        for (int k=0;k<64;k++){
            float vs = Mb[k*64 + lj];
            float wkv = ((k==0) ? w0[lj] : RK[(k-1)*RKS+lj]) * betav[k]*dexpv[k];
            #pragma unroll
            for (int ii=0; ii<16; ii++){
                float a = Am[(g+4*ii)*64 + k];
                accv[ii] += a*vs;
                accw[ii] += a*wkv;
            }
        }
        #pragma unroll
        for (int ii=0; ii<16; ii++){
            int i = g + 4*ii;
            g_vc[base + i*64 + lj]   = accv[ii];
            g_wkcd[base + i*64 + lj] = accw[ii];
        }
    }
}

// ---------------- sequential inter-chunk scan ----------------
#define SCAN_SMEM ((7*4096 + 64 + 16)*4)

__global__ __launch_bounds__(256) void scan_kernel()
{
    extern __shared__ float sm[];
    float* S     = sm;
    float* VN    = S + 4096;
    float* VC    = VN + 4096;
    float* WKCD  = VC + 4096;
    float* RKD   = WKCD + 4096;
    float* INTRA = RKD + 4096;
    float* WKDW  = INTRA + 4096;
    float* gatev = WKDW + 4096;
    float* misc  = gatev + 64;

    int bh = blockIdx.x;
    int b = bh >> 4, h = bh & 15;
    int t = threadIdx.x;
    int lane = t & 31, w = t >> 5;
    int ebl = (t & 15) * 4;
    int cbl = (t >> 4) * 4;

    for (int idx=t; idx<4096; idx+=256) S[idx]=0.f;
    __syncthreads();

    for (int n=0; n<64; n++){
        size_t gb = ((size_t)bh*64 + n)*4096;
        for (int i=t; i<1024; i+=256) {
            ((float4*)VC)[i]    = ((const float4*)(g_vc+gb))[i];
            ((float4*)WKCD)[i]  = ((const float4*)(g_wkcd+gb))[i];
            ((float4*)RKD)[i]   = ((const float4*)(g_rkd+gb))[i];
            ((float4*)INTRA)[i] = ((const float4*)(g_intra+gb))[i];
            ((float4*)WKDW)[i]  = ((const float4*)(g_wkdw+gb))[i];
        }
        if (t < 64) gatev[t] = g_gate[((size_t)b*T_ + n*64 + t)*H_ + h];
        if (t == 0) misc[8] = g_elast[bh*64 + n];
        __syncthreads();

        {
            float acc[4][4];
            #pragma unroll
            for (int ci=0;ci<4;ci++){
                float4 v = *(float4*)&VC[(cbl+ci)*64 + ebl];
                acc[ci][0]=v.x; acc[ci][1]=v.y; acc[ci][2]=v.z; acc[ci][3]=v.w;
            }
            #pragma unroll 8
            for (int k=0;k<64;k++){
                float4 s = *(float4*)&S[k*64 + ebl];
                #pragma unroll
                for (int ci=0;ci<4;ci++){
                    float wv = WKCD[(cbl+ci)*64 + k];
                    acc[ci][0] -= wv*s.x; acc[ci][1] -= wv*s.y;
                    acc[ci][2] -= wv*s.z; acc[ci][3] -= wv*s.w;
                }
            }
            #pragma unroll
            for (int ci=0;ci<4;ci++)
                *(float4*)&VN[(cbl+ci)*64 + ebl] =
                    make_float4(acc[ci][0],acc[ci][1],acc[ci][2],acc[ci][3]);
        }
        __syncthreads();

        float upd[4][4];
        {
            float oa[4][4];
            #pragma unroll
            for (int ci=0;ci<4;ci++)
                #pragma unroll
                for (int ei=0;ei<4;ei++){ oa[ci][ei]=0.f; upd[ci][ei]=0.f; }
            #pragma unroll 8
            for (int k=0;k<64;k++){
                float4 s = *(float4*)&S[k*64 + ebl];
                #pragma unroll
                for (int ci=0;ci<4;ci++){
                    float wv = RKD[(cbl+ci)*64 + k];
                    oa[ci][0] += wv*s.x; oa[ci][1] += wv*s.y;
                    oa[ci][2] += wv*s.z; oa[ci][3] += wv*s.w;
                }
            }
            #pragma unroll 8
            for (int k=0;k<64;k++){
                float4 v = *(float4*)&VN[k*64 + ebl];
                #pragma unroll
                for (int ci=0;ci<4;ci++){
                    float wv = INTRA[(cbl+ci)*64 + k];
                    oa[ci][0] += wv*v.x; oa[ci][1] += wv*v.y;
                    oa[ci][2] += wv*v.z; oa[ci][3] += wv*v.w;
                }
                #pragma unroll
                for (int di=0;di<4;di++){
                    float wd = WKDW[k*64 + cbl + di];
                    upd[di][0] += wd*v.x; upd[di][1] += wd*v.y;
                    upd[di][2] += wd*v.z; upd[di][3] += wd*v.w;
                }
            }
            #pragma unroll
            for (int ci=0;ci<4;ci++){
                float gt = gatev[cbl+ci];
                size_t orow = ((size_t)b*T_ + n*64 + cbl+ci)*D_ + (size_t)h*64 + ebl;
                *(float4*)&g_og[orow] = make_float4(oa[ci][0]*gt, oa[ci][1]*gt,
                                                    oa[ci][2]*gt, oa[ci][3]*gt);
            }
        }
        __syncthreads();

        float el = misc[8];
        float partial = 0.f;
        #pragma unroll
        for (int di=0;di<4;di++){
            #pragma unroll
            for (int ei=0;ei<4;ei++){
                int idx = (cbl+di)*64 + ebl + ei;
                float sv = S[idx]*el + upd[di][ei];
                S[idx] = sv;
                partial += sv*sv;
            }
        }
        #pragma unroll
        for (int off=16; off>0; off>>=1) partial += __shfl_down_sync(0xffffffffu, partial, off);
        if (lane==0) misc[w] = partial;
        __syncthreads();
        if (t==0){
            float s=0.f;
            #pragma unroll
            for (int i=0;i<8;i++) s += misc[i];
            float nrm = sqrtf(s);
            misc[9] = fminf(nrm,100.f)/fmaxf(nrm,1e-6f);
        }
        __syncthreads();
        float f = misc[9];
        #pragma unroll
        for (int di=0;di<4;di++)
            #pragma unroll
            for (int ei=0;ei<4;ei++)
                S[(cbl+di)*64 + ebl + ei] *= f;
        __syncthreads();
    }
}

extern "C" void kernel_launch(void* const* d_in, const int* in_sizes, int n_in,
                              void* d_out, int out_size) {
    const float* x      = (const float*)d_in[0];
    const float* w_wr   = (const float*)d_in[1];
    const float* w_gate = (const float*)d_in[2];
    const float* w_out  = (const float*)d_in[3];
    const float* w_beta = (const float*)d_in[4];
    const float* w_alph = (const float*)d_in[5];
    const float* dtb    = (const float*)d_in[6];
    const float* alog   = (const float*)d_in[7];
    float* out = (float*)d_out;

    cudaFuncSetAttribute(prep_kernel, cudaFuncAttributeMaxDynamicSharedMemorySize, PREP_SMEM);
    cudaFuncSetAttribute(scan_kernel, cudaFuncAttributeMaxDynamicSharedMemorySize, SCAN_SMEM);
    cudaFuncSetAttribute(tgemm_nn,    cudaFuncAttributeMaxDynamicSharedMemorySize, GEMM_SMEM);

    proj_kernel<<<BT_, 256>>>(x, w_gate, w_beta, w_alph, dtb, alog);
    tgemm_nn<<<dim3(8,128), 256, GEMM_SMEM>>>(x, w_wr, nullptr, nullptr, 0);
    prep_kernel<<<BHN_, 256, PREP_SMEM>>>(x);
    scan_kernel<<<64, 256, SCAN_SMEM>>>();
    tgemm_nn<<<dim3(8,128), 256, GEMM_SMEM>>>(nullptr, w_out, x, out, 1);
}

// round 6
// speedup vs baseline: 2.5464x; 2.3287x over previous
#include <cuda_runtime.h>
#include <cuda_bf16.h>
#include <math.h>
#include <stdint.h>

#define B_ 4
#define T_ 4096
#define D_ 1024
#define H_ 16
#define C_ 64
#define N_ 64
#define BT_ (B_*T_)
#define BHN_ (B_*H_*N_)

// ---------- scratch ----------
__device__ float g_v[BT_*D_];
__device__ float g_og[BT_*D_];
__device__ float g_gate[BT_*H_];
__device__ float g_beta[BT_*H_];
__device__ float g_dec[BT_*H_];
__device__ float g_rkd[BHN_*4096];
__device__ float g_wkcd[BHN_*4096];
__device__ float g_vc[BHN_*4096];
__device__ float g_wkdw[BHN_*4096];
__device__ float g_intra[BHN_*4096];
__device__ float g_elast[BHN_];

__device__ __forceinline__ uint32_t smem_u32(const void* p){
    uint32_t a;
    asm("{ .reg .u64 t; cvta.to.shared.u64 t, %1; cvt.u32.u64 %0, t; }" : "=r"(a) : "l"(p));
    return a;
}

// ================= projections (tiled coalesced GEMM, 48 outputs) =================
#define XS_STRIDE 132
#define PROJ_SMEM ((128*XS_STRIDE + 128*48)*4)
__global__ __launch_bounds__(256) void proj_kernel(
    const float* __restrict__ x, const float* __restrict__ wg,
    const float* __restrict__ wb, const float* __restrict__ wa,
    const float* __restrict__ dtb, const float* __restrict__ alog)
{
    extern __shared__ float psm[];
    float* Xs = psm;                    // [128][132]
    float* Ws = psm + 128*XS_STRIDE;    // [128][48]
    int t = threadIdx.x;
    int row = t & 127, og = t >> 7;
    int o0 = og*24;
    int r0 = blockIdx.x * 128;

    float acc[24];
    #pragma unroll
    for (int j=0;j<24;j++) acc[j]=0.f;

    for (int k0=0; k0<1024; k0+=128){
        #pragma unroll
        for (int i=0;i<16;i++){
            int f4 = i*256 + t;
            int m = f4 >> 5, kv = (f4 & 31)*4;
            float4 v = *(const float4*)&x[(size_t)(r0+m)*1024 + k0 + kv];
            *(float4*)&Xs[m*XS_STRIDE + kv] = v;
        }
        for (int e = t; e < 128*48; e += 256){
            int kk = e / 48, o = e % 48;
            const float* W = (o<16) ? wg : ((o<32) ? wb : wa);
            Ws[kk*48 + o] = W[(size_t)(k0+kk)*16 + (o & 15)];
        }
        __syncthreads();
        #pragma unroll 4
        for (int kk=0; kk<128; kk++){
            float xv = Xs[row*XS_STRIDE + kk];
            const float* wrow = &Ws[kk*48 + o0];
            #pragma unroll
            for (int j=0;j<24;j+=4){
                float4 w4 = *(const float4*)&wrow[j];
                acc[j]   += xv*w4.x; acc[j+1] += xv*w4.y;
                acc[j+2] += xv*w4.z; acc[j+3] += xv*w4.w;
            }
        }
        __syncthreads();
    }
    int rg = r0 + row;
    #pragma unroll
    for (int j=0;j<24;j++){
        int o = o0 + j;
        int h = o & 15, kind = o >> 4;
        float s = acc[j];
        if (kind==0)      g_gate[rg*16+h] = 1.f/(1.f+__expf(-s));
        else if (kind==1) g_beta[rg*16+h] = 1.f/(1.f+__expf(-s));
        else {
            float v = s + dtb[h];
            float sp = fmaxf(v,0.f) + log1pf(__expf(-fabsf(v)));
            g_dec[rg*16+h] = -__expf(alog[h])*sp;
        }
    }
}

// ================= bf16 mma.sync GEMM (family-safe tensor path) =================
// C(16384,1024) = A @ W (+R). 128x128 tile, BK=32, 8 warps (4x2), m16n8k16.
#define GS_A_STRIDE 20                   // words per A row (16 data + 4 pad)
#define GS_B_STRIDE 68                   // words per B k-row (64 data + 4 pad)
#define GS_A_TILE  (128*GS_A_STRIDE)     // 2560 words
#define GS_B_TILE  (32*GS_B_STRIDE)      // 2176 words
#define GS_STAGE   (GS_A_TILE + GS_B_TILE)
#define G_SMEM     (2*GS_STAGE*4)

__device__ __forceinline__ void ldsm4(unsigned r[4], uint32_t a){
    asm volatile("ldmatrix.sync.aligned.m8n8.x4.shared.b16 {%0,%1,%2,%3}, [%4];"
        : "=r"(r[0]),"=r"(r[1]),"=r"(r[2]),"=r"(r[3]) : "r"(a));
}
__device__ __forceinline__ void ldsm4t(unsigned r[4], uint32_t a){
    asm volatile("ldmatrix.sync.aligned.m8n8.x4.trans.shared.b16 {%0,%1,%2,%3}, [%4];"
        : "=r"(r[0]),"=r"(r[1]),"=r"(r[2]),"=r"(r[3]) : "r"(a));
}
__device__ __forceinline__ void mma_bf16(float* c, const unsigned* a, unsigned b0, unsigned b1){
    asm volatile("mma.sync.aligned.m16n8k16.row.col.f32.bf16.bf16.f32 "
      "{%0,%1,%2,%3}, {%4,%5,%6,%7}, {%8,%9}, {%0,%1,%2,%3};"
      : "+f"(c[0]),"+f"(c[1]),"+f"(c[2]),"+f"(c[3])
      : "r"(a[0]),"r"(a[1]),"r"(a[2]),"r"(a[3]),"r"(b0),"r"(b1));
}

__global__ __launch_bounds__(256) void hgemm(
    const float* Ain, const float* __restrict__ Bw,
    const float* __restrict__ R, float* Cout, int mode)
{
    extern __shared__ float gsm[];
    uint32_t sbase = smem_u32(gsm);
    const float* A = mode ? (const float*)g_og : Ain;
    float* C = mode ? Cout : (float*)g_v;

    int t = threadIdx.x, lane = t & 31, warp = t >> 5;
    int wm = warp >> 1, wn = warp & 1;
    int bm = blockIdx.y, bn = blockIdx.x;
    const float* Ab = A + (size_t)(bm*128)*1024;
    const float* Bb = Bw + (size_t)bn*128;

    int arow = t >> 3, ac4 = t & 7;   // A: row arow+u*32, float4 col ac4
    int bk = t >> 5, bn4 = t & 31;    // B: k bk+u*8, float4 col bn4

    float4 aReg[4], bReg[4];
    float acc[2][8][4];
    #pragma unroll
    for (int mt=0;mt<2;mt++)
        #pragma unroll
        for (int j=0;j<8;j++)
            #pragma unroll
            for (int r=0;r<4;r++) acc[mt][j][r]=0.f;

    auto ldg = [&](int it){
        #pragma unroll
        for (int u=0;u<4;u++){
            aReg[u] = *(const float4*)&Ab[(size_t)(u*32 + arow)*1024 + it*32 + ac4*4];
            bReg[u] = *(const float4*)&Bb[(size_t)(it*32 + u*8 + bk)*1024 + bn4*4];
        }
    };
    auto sts = [&](int p){
        uint32_t sa = sbase + (uint32_t)p*GS_STAGE*4;
        uint32_t sb = sa + GS_A_TILE*4;
        #pragma unroll
        for (int u=0;u<4;u++){
            __nv_bfloat162 lo = __floats2bfloat162_rn(aReg[u].x, aReg[u].y);
            __nv_bfloat162 hi = __floats2bfloat162_rn(aReg[u].z, aReg[u].w);
            uint32_t off = sa + (uint32_t)(((u*32+arow)*GS_A_STRIDE + ac4*2)*4);
            asm volatile("st.shared.v2.b32 [%0], {%1,%2};" :: "r"(off),
                "r"(*(unsigned*)&lo), "r"(*(unsigned*)&hi) : "memory");
            __nv_bfloat162 blo = __floats2bfloat162_rn(bReg[u].x, bReg[u].y);
            __nv_bfloat162 bhi = __floats2bfloat162_rn(bReg[u].z, bReg[u].w);
            uint32_t boff = sb + (uint32_t)(((u*8+bk)*GS_B_STRIDE + bn4*2)*4);
            asm volatile("st.shared.v2.b32 [%0], {%1,%2};" :: "r"(boff),
                "r"(*(unsigned*)&blo), "r"(*(unsigned*)&bhi) : "memory");
        }
    };

    ldg(0); sts(0); __syncthreads();

    for (int it=0; it<32; it++){
        int p = it & 1;
        if (it < 31) ldg(it+1);
        uint32_t sa = sbase + (uint32_t)p*GS_STAGE*4;
        uint32_t sb = sa + GS_A_TILE*4;
        #pragma unroll
        for (int s=0;s<2;s++){
            unsigned af[2][4], bfr[4][4];
            #pragma unroll
            for (int mt=0;mt<2;mt++){
                uint32_t ad = sa + (uint32_t)((((wm*32 + mt*16 + (lane&15))*GS_A_STRIDE)
                                  + s*8 + ((lane>>4)&1)*4)*4);
                ldsm4(af[mt], ad);
            }
            #pragma unroll
            for (int nt=0;nt<4;nt++){
                uint32_t bd = sb + (uint32_t)((((s*16 + (lane&7) + ((lane>>3)&1)*8)*GS_B_STRIDE)
                                  + wn*32 + nt*8 + ((lane>>4)&1)*4)*4);
                ldsm4t(bfr[nt], bd);
            }
            #pragma unroll
            for (int mt=0;mt<2;mt++)
                #pragma unroll
                for (int j=0;j<8;j++)
                    mma_bf16(acc[mt][j], af[mt], bfr[j>>1][(j&1)*2], bfr[j>>1][(j&1)*2+1]);
        }
        __syncthreads();
        if (it < 31){ sts(p^1); __syncthreads(); }
    }

    int g = lane >> 2, tg = lane & 3;
    #pragma unroll
    for (int mt=0; mt<2; mt++){
        int r0 = bm*128 + wm*32 + mt*16 + g;
        #pragma unroll
        for (int j=0; j<8; j++){
            int col = bn*128 + wn*64 + j*8 + tg*2;
            size_t o0 = (size_t)r0*1024 + col;
            size_t o1 = o0 + (size_t)8*1024;
            float2 v0 = make_float2(acc[mt][j][0], acc[mt][j][1]);
            float2 v1 = make_float2(acc[mt][j][2], acc[mt][j][3]);
            if (mode){
                float2 q0 = *(const float2*)&R[o0];
                float2 q1 = *(const float2*)&R[o1];
                v0.x += q0.x; v0.y += q0.y; v1.x += q1.x; v1.y += q1.y;
            }
            *(float2*)&C[o0] = v0;
            *(float2*)&C[o1] = v1;
        }
    }
}

// ================= per-chunk prep =================
#define RKS 65
#define PREP_SMEM ((64*RKS + 64*64 + 64*64 + 64*4 + 8)*4)
__global__ __launch_bounds__(256) void prep_kernel(const float* __restrict__ x)
{
    extern __shared__ float sm[];
    float* RK    = sm;
    float* Mb    = RK + 64*RKS;
    float* Am    = Mb + 64*64;
    float* cum   = Am + 64*64;
    float* dexpv = cum + 64;
    float* betav = dexpv + 64;
    float* w0    = betav + 64;
    float* extra = w0 + 64;

    int cid = blockIdx.x;
    int b = cid / (H_*N_);
    int h = (cid / N_) % H_;
    int n = cid % N_;
    int t = threadIdx.x;
    int lj = t & 63;
    int g  = t >> 6;
    size_t xbase = ((size_t)b*T_ + (size_t)n*C_)*D_ + (size_t)h*64;
    size_t base  = (size_t)cid*4096;

    for (int idx=t; idx<4096; idx+=256) {
        int c = idx>>6, j = idx&63;
        RK[c*RKS + j] = x[xbase + (size_t)c*D_ + j];
    }
    if (t < 64) {
        int tok = (b*T_ + n*C_ + t)*H_ + h;
        betav[t] = g_beta[tok];
        cum[t]   = g_dec[tok];
    }
    if (t >= 64 && t < 128) {
        int j = t - 64;
        w0[j] = (n > 0) ? x[xbase - D_ + j] : 0.f;
    }
    __syncthreads();

    if (t < 64) {
        float s = 0.f;
        for (int j=0;j<64;j++){ float v = RK[t*RKS+j]; s += v*v; }
        float inv = 1.f/fmaxf(sqrtf(s), 1e-12f);
        for (int j=0;j<64;j++) RK[t*RKS+j] *= inv;
    }
    if (t == 64) {
        float s = 0.f;
        for (int j=0;j<64;j++) s += w0[j]*w0[j];
        extra[0] = 1.f/fmaxf(sqrtf(s), 1e-12f);
    }
    if (t == 65) {
        float s = 0.f;
        for (int c=0;c<64;c++){ s += cum[c]; cum[c] = s; }
    }
    __syncthreads();
    if (t < 64) {
        w0[t] *= extra[0];
        dexpv[t] = __expf(cum[t]);
    }
    __syncthreads();

    {
        const float* rowPtr[16];
        #pragma unroll
        for (int ii=0; ii<16; ii++) {
            int i = g + 4*ii;
            rowPtr[ii] = (i==0) ? w0 : &RK[(i-1)*RKS];
        }
        const float* rowk = (lj==0) ? w0 : &RK[(lj-1)*RKS];
        float acc[16];
        #pragma unroll
        for (int ii=0; ii<16; ii++) acc[ii]=0.f;
        for (int m=0;m<64;m++){
            float wkm = rowk[m];
            #pragma unroll
            for (int ii=0; ii<16; ii++) acc[ii] += rowPtr[ii][m]*wkm;
        }
        #pragma unroll
        for (int ii=0; ii<16; ii++){
            int i = g + 4*ii;
            Mb[i*64 + lj] = (lj < i) ? (-betav[i]*__expf(cum[i]-cum[lj])*acc[ii]) : 0.f;
        }
    }
    __syncthreads();

    for (int idx=t; idx<4096; idx+=256)
        Am[idx] = ((idx>>6)==(idx&63)) ? 1.f : 0.f;
    __syncthreads();
    for (int k=0;k<63;k++){
        for (int i=k+1+g; i<64; i+=4)
            Am[i*64+lj] += Mb[i*64+k]*Am[k*64+lj];
        __syncthreads();
    }

    {
        const float* rowPtr[16];
        #pragma unroll
        for (int ii=0; ii<16; ii++) rowPtr[ii] = &RK[(g+4*ii)*RKS];
        const float* rowj = (lj==0) ? w0 : &RK[(lj-1)*RKS];
        float acc[16];
        #pragma unroll
        for (int ii=0; ii<16; ii++) acc[ii]=0.f;
        for (int m=0;m<64;m++){
            float wjm = rowj[m];
            #pragma unroll
            for (int ii=0; ii<16; ii++) acc[ii] += rowPtr[ii][m]*wjm;
        }
        #pragma unroll
        for (int ii=0; ii<16; ii++){
            int i = g + 4*ii;
            g_intra[base + i*64 + lj] = (i >= lj) ? (__expf(cum[i]-cum[lj])*acc[ii]) : 0.f;
        }
    }
    float cum63 = cum[63];
    for (int idx=t; idx<4096; idx+=256){
        int c = idx>>6, j = idx&63;
        g_rkd[base+idx] = RK[c*RKS+j]*dexpv[c];
        float wcj = (c==0) ? w0[j] : RK[(c-1)*RKS+j];
        g_wkdw[base+idx] = wcj*__expf(cum63 - cum[c]);
    }
    if (t==0) g_elast[cid] = __expf(cum63);

    for (int idx=t; idx<4096; idx+=256){
        int c = idx>>6, j = idx&63;
        Mb[c*64+j] = g_v[xbase + (size_t)c*D_ + j]*betav[c];
    }
    __syncthreads();

    {
        float accv[16], accw[16];
        #pragma unroll
        for (int ii=0; ii<16; ii++){ accv[ii]=0.f; accw[ii]=0.f; }
        for (int k=0;k<64;k++){
            float vs = Mb[k*64 + lj];
            float wkv = ((k==0) ? w0[lj] : RK[(k-1)*RKS+lj]) * betav[k]*dexpv[k];
            #pragma unroll
            for (int ii=0; ii<16; ii++){
                float a = Am[(g+4*ii)*64 + k];
                accv[ii] += a*vs;
                accw[ii] += a*wkv;
            }
        }
        #pragma unroll
        for (int ii=0; ii<16; ii++){
            int i = g + 4*ii;
            g_vc[base + i*64 + lj]   = accv[ii];
            g_wkcd[base + i*64 + lj] = accw[ii];
        }
    }
}

// ================= scan: cluster of 2, split e-dim =================
#define SS 36
#define TS 68
#define SCAN_SMEM ((3*64*SS + 3*64*TS + 64*64 + 64 + 32)*4)

__global__ __launch_bounds__(256) __cluster_dims__(2,1,1) void scan_kernel()
{
    extern __shared__ float sm[];
    float* S     = sm;
    float* VN    = S + 64*SS;
    float* VC    = VN + 64*SS;
    float* WKCD  = VC + 64*SS;
    float* RKD   = WKCD + 64*TS;
    float* INTRA = RKD + 64*TS;
    float* WKDW  = INTRA + 64*TS;
    float* gatev = WKDW + 64*64;
    float* misc  = gatev + 64;

    int bid = blockIdx.x;
    int bh = bid >> 1, half = bid & 1;
    int b = bh >> 4, h = bh & 15;
    int t = threadIdx.x;
    int lane = t & 31, w = t >> 5;
    int ebl = (t & 7) * 4;
    int cbl = (t >> 3) * 2;

    uint32_t exch_addr = smem_u32(&misc[10]);
    uint32_t peer = half ^ 1;

    for (int i=t; i<64*SS; i+=256) S[i]=0.f;
    __syncthreads();

    for (int n=0; n<64; n++){
        size_t gb = ((size_t)bh*64 + n)*4096;
        #pragma unroll
        for (int u=0; u<4; u++){
            int q = u*256 + t;
            int c = q >> 4, jv = (q & 15)*4;
            int so = c*TS + jv;
            *(float4*)&WKCD[so]  = *(const float4*)&g_wkcd[gb + c*64 + jv];
            *(float4*)&RKD[so]   = *(const float4*)&g_rkd[gb + c*64 + jv];
            *(float4*)&INTRA[so] = *(const float4*)&g_intra[gb + c*64 + jv];
            ((float4*)WKDW)[q]   = ((const float4*)(g_wkdw+gb))[q];
        }
        #pragma unroll
        for (int u=0; u<2; u++){
            int q = u*256 + t;
            int c = q >> 3, jv = (q & 7)*4;
            *(float4*)&VC[c*SS + jv] = *(const float4*)&g_vc[gb + c*64 + half*32 + jv];
        }
        if (t < 64) gatev[t] = g_gate[((size_t)b*T_ + n*64 + t)*H_ + h];
        if (t == 0) misc[8] = g_elast[bh*64 + n];
        __syncthreads();

        {
            float acc[2][4];
            #pragma unroll
            for (int ci=0;ci<2;ci++){
                float4 v = *(float4*)&VC[(cbl+ci)*SS + ebl];
                acc[ci][0]=v.x; acc[ci][1]=v.y; acc[ci][2]=v.z; acc[ci][3]=v.w;
            }
            #pragma unroll 8
            for (int k=0;k<64;k++){
                float4 s = *(float4*)&S[k*SS + ebl];
                #pragma unroll
                for (int ci=0;ci<2;ci++){
                    float wv = WKCD[(cbl+ci)*TS + k];
                    acc[ci][0] -= wv*s.x; acc[ci][1] -= wv*s.y;
                    acc[ci][2] -= wv*s.z; acc[ci][3] -= wv*s.w;
                }
            }
            #pragma unroll
            for (int ci=0;ci<2;ci++)
                *(float4*)&VN[(cbl+ci)*SS + ebl] =
                    make_float4(acc[ci][0],acc[ci][1],acc[ci][2],acc[ci][3]);
        }
        __syncthreads();

        float upd[2][4];
        {
            float oa[2][4];
            #pragma unroll
            for (int ci=0;ci<2;ci++)
                #pragma unroll
                for (int ei=0;ei<4;ei++){ oa[ci][ei]=0.f; upd[ci][ei]=0.f; }
            #pragma unroll 8
            for (int k=0;k<64;k++){
                float4 s = *(float4*)&S[k*SS + ebl];
                #pragma unroll
                for (int ci=0;ci<2;ci++){
                    float wv = RKD[(cbl+ci)*TS + k];
                    oa[ci][0] += wv*s.x; oa[ci][1] += wv*s.y;
                    oa[ci][2] += wv*s.z; oa[ci][3] += wv*s.w;
                }
            }
            #pragma unroll 8
            for (int k=0;k<64;k++){
                float4 v = *(float4*)&VN[k*SS + ebl];
                #pragma unroll
                for (int ci=0;ci<2;ci++){
                    float wv = INTRA[(cbl+ci)*TS + k];
                    oa[ci][0] += wv*v.x; oa[ci][1] += wv*v.y;
                    oa[ci][2] += wv*v.z; oa[ci][3] += wv*v.w;
                }
                #pragma unroll
                for (int di=0;di<2;di++){
                    float wd = WKDW[k*64 + cbl + di];
                    upd[di][0] += wd*v.x; upd[di][1] += wd*v.y;
                    upd[di][2] += wd*v.z; upd[di][3] += wd*v.w;
                }
            }
            #pragma unroll
            for (int ci=0;ci<2;ci++){
                float gt = gatev[cbl+ci];
                size_t orow = ((size_t)b*T_ + n*64 + cbl+ci)*D_ + (size_t)h*64 + half*32 + ebl;
                *(float4*)&g_og[orow] = make_float4(oa[ci][0]*gt, oa[ci][1]*gt,
                                                    oa[ci][2]*gt, oa[ci][3]*gt);
            }
        }
        __syncthreads();

        float el = misc[8];
        float partial = 0.f;
        #pragma unroll
        for (int di=0;di<2;di++){
            #pragma unroll
            for (int ei=0;ei<4;ei++){
                int idx = (cbl+di)*SS + ebl + ei;
                float sv = S[idx]*el + upd[di][ei];
                S[idx] = sv;
                partial += sv*sv;
            }
        }
        #pragma unroll
        for (int off=16; off>0; off>>=1) partial += __shfl_down_sync(0xffffffffu, partial, off);
        if (lane==0) misc[w] = partial;
        __syncthreads();
        if (t==0){
            float s=0.f;
            #pragma unroll
            for (int i=0;i<8;i++) s += misc[i];
            misc[9] = s;
            uint32_t remote;
            asm volatile("mapa.shared::cluster.u32 %0, %1, %2;" : "=r"(remote)
                         : "r"(exch_addr + (n&1)*4), "r"(peer));
            asm volatile("st.shared::cluster.f32 [%0], %1;" :: "r"(remote), "f"(s) : "memory");
        }
        asm volatile("barrier.cluster.arrive.aligned;" ::: "memory");
        asm volatile("barrier.cluster.wait.aligned;" ::: "memory");
        float total = misc[9] + misc[10 + (n&1)];
        float nrm = sqrtf(total);
        float f = fminf(nrm,100.f)/fmaxf(nrm,1e-6f);
        #pragma unroll
        for (int di=0;di<2;di++)
            #pragma unroll
            for (int ei=0;ei<4;ei++)
                S[(cbl+di)*SS + ebl + ei] *= f;
        __syncthreads();
    }
}

extern "C" void kernel_launch(void* const* d_in, const int* in_sizes, int n_in,
                              void* d_out, int out_size) {
    const float* x      = (const float*)d_in[0];
    const float* w_wr   = (const float*)d_in[1];
    const float* w_gate = (const float*)d_in[2];
    const float* w_out  = (const float*)d_in[3];
    const float* w_beta = (const float*)d_in[4];
    const float* w_alph = (const float*)d_in[5];
    const float* dtb    = (const float*)d_in[6];
    const float* alog   = (const float*)d_in[7];
    float* out = (float*)d_out;

    cudaFuncSetAttribute(proj_kernel, cudaFuncAttributeMaxDynamicSharedMemorySize, PROJ_SMEM);
    cudaFuncSetAttribute(prep_kernel, cudaFuncAttributeMaxDynamicSharedMemorySize, PREP_SMEM);
    cudaFuncSetAttribute(scan_kernel, cudaFuncAttributeMaxDynamicSharedMemorySize, SCAN_SMEM);
    cudaFuncSetAttribute(hgemm,       cudaFuncAttributeMaxDynamicSharedMemorySize, G_SMEM);

    proj_kernel<<<128, 256, PROJ_SMEM>>>(x, w_gate, w_beta, w_alph, dtb, alog);
    hgemm<<<dim3(8,128), 256, G_SMEM>>>(x, w_wr, nullptr, nullptr, 0);
    prep_kernel<<<BHN_, 256, PREP_SMEM>>>(x);
    scan_kernel<<<128, 256, SCAN_SMEM>>>();
    hgemm<<<dim3(8,128), 256, G_SMEM>>>(nullptr, w_out, x, out, 1);
}

// round 7
// speedup vs baseline: 2.5736x; 1.0107x over previous
#include <cuda_runtime.h>
#include <cuda_bf16.h>
#include <math.h>
#include <stdint.h>

#define B_ 4
#define T_ 4096
#define D_ 1024
#define H_ 16
#define C_ 64
#define N_ 64
#define BT_ (B_*T_)
#define BHN_ (B_*H_*N_)

// ---------- scratch ----------
__device__ float g_v[BT_*D_];
__device__ float g_og[BT_*D_];
__device__ float g_gate[BT_*H_];
__device__ float g_beta[BT_*H_];
__device__ float g_dec[BT_*H_];
__device__ float g_rkd[BHN_*4096];
__device__ float g_wkcd[BHN_*4096];
__device__ float g_vc[BHN_*4096];
__device__ float g_wkdw[BHN_*4096];   // TRANSPOSED: [d][token] per chunk
__device__ float g_intra[BHN_*4096];
__device__ float g_elast[BHN_];
__device__ __nv_bfloat16 g_xb[BT_*D_];
__device__ __nv_bfloat16 g_ogb[BT_*D_];
__device__ __nv_bfloat16 g_wb0[D_*D_];
__device__ __nv_bfloat16 g_wb1[D_*D_];

__device__ __forceinline__ uint32_t smem_u32(const void* p){
    uint32_t a;
    asm("{ .reg .u64 t; cvta.to.shared.u64 t, %1; cvt.u32.u64 %0, t; }" : "=r"(a) : "l"(p));
    return a;
}

// ---------------- fp32 -> bf16 convert ----------------
__global__ __launch_bounds__(256) void cvt_kernel(const float* __restrict__ in,
                                                  __nv_bfloat16* __restrict__ out, int n4)
{
    int i = blockIdx.x*256 + threadIdx.x;
    if (i < n4){
        float4 v = ((const float4*)in)[i];
        __nv_bfloat162 a = __floats2bfloat162_rn(v.x, v.y);
        __nv_bfloat162 b = __floats2bfloat162_rn(v.z, v.w);
        ((__nv_bfloat162*)out)[2*i]   = a;
        ((__nv_bfloat162*)out)[2*i+1] = b;
    }
}

// ================= projections =================
#define XS_STRIDE 132
#define PROJ_SMEM ((128*XS_STRIDE + 128*48)*4)
__global__ __launch_bounds__(256) void proj_kernel(
    const float* __restrict__ x, const float* __restrict__ wg,
    const float* __restrict__ wb, const float* __restrict__ wa,
    const float* __restrict__ dtb, const float* __restrict__ alog)
{
    extern __shared__ float psm[];
    float* Xs = psm;
    float* Ws = psm + 128*XS_STRIDE;
    int t = threadIdx.x;
    int row = t & 127, og = t >> 7;
    int o0 = og*24;
    int r0 = blockIdx.x * 128;

    float acc[24];
    #pragma unroll
    for (int j=0;j<24;j++) acc[j]=0.f;

    for (int k0=0; k0<1024; k0+=128){
        #pragma unroll
        for (int i=0;i<16;i++){
            int f4 = i*256 + t;
            int m = f4 >> 5, kv = (f4 & 31)*4;
            float4 v = *(const float4*)&x[(size_t)(r0+m)*1024 + k0 + kv];
            *(float4*)&Xs[m*XS_STRIDE + kv] = v;
        }
        for (int e = t; e < 128*48; e += 256){
            int kk = e / 48, o = e % 48;
            const float* W = (o<16) ? wg : ((o<32) ? wb : wa);
            Ws[kk*48 + o] = W[(size_t)(k0+kk)*16 + (o & 15)];
        }
        __syncthreads();
        #pragma unroll 4
        for (int kk=0; kk<128; kk++){
            float xv = Xs[row*XS_STRIDE + kk];
            const float* wrow = &Ws[kk*48 + o0];
            #pragma unroll
            for (int j=0;j<24;j+=4){
                float4 w4 = *(const float4*)&wrow[j];
                acc[j]   += xv*w4.x; acc[j+1] += xv*w4.y;
                acc[j+2] += xv*w4.z; acc[j+3] += xv*w4.w;
            }
        }
        __syncthreads();
    }
    int rg = r0 + row;
    #pragma unroll
    for (int j=0;j<24;j++){
        int o = o0 + j;
        int h = o & 15, kind = o >> 4;
        float s = acc[j];
        if (kind==0)      g_gate[rg*16+h] = 1.f/(1.f+__expf(-s));
        else if (kind==1) g_beta[rg*16+h] = 1.f/(1.f+__expf(-s));
        else {
            float v = s + dtb[h];
            float sp = fmaxf(v,0.f) + log1pf(__expf(-fabsf(v)));
            g_dec[rg*16+h] = -__expf(alog[h])*sp;
        }
    }
}

// ================= bf16 mma GEMM, cp.async 4-stage =================
#define GS_A_STRIDE 20
#define GS_B_STRIDE 68
#define GS_A_TILE  (128*GS_A_STRIDE)
#define GS_B_TILE  (32*GS_B_STRIDE)
#define GS_STAGE   (GS_A_TILE + GS_B_TILE)
#define G_SMEM     (4*GS_STAGE*4)

__device__ __forceinline__ void ldsm4(unsigned r[4], uint32_t a){
    asm volatile("ldmatrix.sync.aligned.m8n8.x4.shared.b16 {%0,%1,%2,%3}, [%4];"
        : "=r"(r[0]),"=r"(r[1]),"=r"(r[2]),"=r"(r[3]) : "r"(a));
}
__device__ __forceinline__ void ldsm4t(unsigned r[4], uint32_t a){
    asm volatile("ldmatrix.sync.aligned.m8n8.x4.trans.shared.b16 {%0,%1,%2,%3}, [%4];"
        : "=r"(r[0]),"=r"(r[1]),"=r"(r[2]),"=r"(r[3]) : "r"(a));
}
__device__ __forceinline__ void mma_bf16(float* c, const unsigned* a, unsigned b0, unsigned b1){
    asm volatile("mma.sync.aligned.m16n8k16.row.col.f32.bf16.bf16.f32 "
      "{%0,%1,%2,%3}, {%4,%5,%6,%7}, {%8,%9}, {%0,%1,%2,%3};"
      : "+f"(c[0]),"+f"(c[1]),"+f"(c[2]),"+f"(c[3])
      : "r"(a[0]),"r"(a[1]),"r"(a[2]),"r"(a[3]),"r"(b0),"r"(b1));
}

__global__ __launch_bounds__(256) void hgemm(
    const __nv_bfloat16* __restrict__ A, const __nv_bfloat16* __restrict__ Bw,
    const float* __restrict__ R, float* __restrict__ C, int mode)
{
    extern __shared__ float gsm[];
    uint32_t sbase = smem_u32(gsm);

    int t = threadIdx.x, lane = t & 31, warp = t >> 5;
    int wm = warp >> 1, wn = warp & 1;
    int bm = blockIdx.y, bn = blockIdx.x;
    const __nv_bfloat16* Ab = A + (size_t)(bm*128)*1024;
    const __nv_bfloat16* Bb = Bw + (size_t)bn*128;

    float acc[2][8][4];
    #pragma unroll
    for (int mt=0;mt<2;mt++)
        #pragma unroll
        for (int j=0;j<8;j++)
            #pragma unroll
            for (int r=0;r<4;r++) acc[mt][j][r]=0.f;

    auto issue = [&](int it){
        uint32_t st = sbase + (uint32_t)(it & 3)*(GS_STAGE*4);
        #pragma unroll
        for (int u=0;u<2;u++){
            int row = u*64 + (t>>2), ch = t&3;
            uint32_t so = st + (uint32_t)((row*GS_A_STRIDE + ch*4)*4);
            const __nv_bfloat16* gp = Ab + (size_t)row*1024 + it*32 + ch*8;
            asm volatile("cp.async.cg.shared.global [%0], [%1], 16;" :: "r"(so), "l"(gp));
        }
        uint32_t sb = st + GS_A_TILE*4;
        #pragma unroll
        for (int u=0;u<2;u++){
            int row = u*16 + (t>>4), ch = t&15;
            uint32_t so = sb + (uint32_t)((row*GS_B_STRIDE + ch*4)*4);
            const __nv_bfloat16* gp = Bb + (size_t)(it*32 + row)*1024 + ch*8;
            asm volatile("cp.async.cg.shared.global [%0], [%1], 16;" :: "r"(so), "l"(gp));
        }
    };

    issue(0); asm volatile("cp.async.commit_group;" ::: "memory");
    issue(1); asm volatile("cp.async.commit_group;" ::: "memory");
    issue(2); asm volatile("cp.async.commit_group;" ::: "memory");

    for (int it=0; it<32; it++){
        asm volatile("cp.async.wait_group 2;" ::: "memory");
        __syncthreads();
        if (it+3 < 32){
            issue(it+3);
            asm volatile("cp.async.commit_group;" ::: "memory");
        }
        uint32_t sa = sbase + (uint32_t)(it & 3)*(GS_STAGE*4);
        uint32_t sb = sa + GS_A_TILE*4;
        #pragma unroll
        for (int s=0;s<2;s++){
            unsigned af[2][4], bfr[4][4];
            #pragma unroll
            for (int mt=0;mt<2;mt++){
                uint32_t ad = sa + (uint32_t)((((wm*32 + mt*16 + (lane&15))*GS_A_STRIDE)
                                  + s*8 + ((lane>>4)&1)*4)*4);
                ldsm4(af[mt], ad);
            }
            #pragma unroll
            for (int nt=0;nt<4;nt++){
                uint32_t bd = sb + (uint32_t)((((s*16 + (lane&7) + ((lane>>3)&1)*8)*GS_B_STRIDE)
                                  + wn*32 + nt*8 + ((lane>>4)&1)*4)*4);
                ldsm4t(bfr[nt], bd);
            }
            #pragma unroll
            for (int mt=0;mt<2;mt++)
                #pragma unroll
                for (int j=0;j<8;j++)
                    mma_bf16(acc[mt][j], af[mt], bfr[j>>1][(j&1)*2], bfr[j>>1][(j&1)*2+1]);
        }
    }

    int g = lane >> 2, tg = lane & 3;
    #pragma unroll
    for (int mt=0; mt<2; mt++){
        int r0 = bm*128 + wm*32 + mt*16 + g;
        #pragma unroll
        for (int j=0; j<8; j++){
            int col = bn*128 + wn*64 + j*8 + tg*2;
            size_t o0 = (size_t)r0*1024 + col;
            size_t o1 = o0 + (size_t)8*1024;
            float2 v0 = make_float2(acc[mt][j][0], acc[mt][j][1]);
            float2 v1 = make_float2(acc[mt][j][2], acc[mt][j][3]);
            if (mode){
                float2 q0 = *(const float2*)&R[o0];
                float2 q1 = *(const float2*)&R[o1];
                v0.x += q0.x; v0.y += q0.y; v1.x += q1.x; v1.y += q1.y;
            }
            *(float2*)&C[o0] = v0;
            *(float2*)&C[o1] = v1;
        }
    }
}

// ================= per-chunk prep =================
#define RKS 65
#define PREP_SMEM ((64*RKS + 64*64 + 64*64 + 64*4 + 8)*4)
__global__ __launch_bounds__(256) void prep_kernel(const float* __restrict__ x)
{
    extern __shared__ float sm[];
    float* RK    = sm;
    float* Mb    = RK + 64*RKS;
    float* Am    = Mb + 64*64;
    float* cum   = Am + 64*64;
    float* dexpv = cum + 64;
    float* betav = dexpv + 64;
    float* w0    = betav + 64;
    float* extra = w0 + 64;

    int cid = blockIdx.x;
    int b = cid / (H_*N_);
    int h = (cid / N_) % H_;
    int n = cid % N_;
    int t = threadIdx.x;
    int lj = t & 63;
    int g  = t >> 6;
    size_t xbase = ((size_t)b*T_ + (size_t)n*C_)*D_ + (size_t)h*64;
    size_t base  = (size_t)cid*4096;

    for (int idx=t; idx<4096; idx+=256) {
        int c = idx>>6, j = idx&63;
        RK[c*RKS + j] = x[xbase + (size_t)c*D_ + j];
    }
    if (t < 64) {
        int tok = (b*T_ + n*C_ + t)*H_ + h;
        betav[t] = g_beta[tok];
        cum[t]   = g_dec[tok];
    }
    if (t >= 64 && t < 128) {
        int j = t - 64;
        w0[j] = (n > 0) ? x[xbase - D_ + j] : 0.f;
    }
    __syncthreads();

    if (t < 64) {
        float s = 0.f;
        for (int j=0;j<64;j++){ float v = RK[t*RKS+j]; s += v*v; }
        float inv = 1.f/fmaxf(sqrtf(s), 1e-12f);
        for (int j=0;j<64;j++) RK[t*RKS+j] *= inv;
    }
    if (t == 64) {
        float s = 0.f;
        for (int j=0;j<64;j++) s += w0[j]*w0[j];
        extra[0] = 1.f/fmaxf(sqrtf(s), 1e-12f);
    }
    if (t == 65) {
        float s = 0.f;
        for (int c=0;c<64;c++){ s += cum[c]; cum[c] = s; }
    }
    __syncthreads();
    if (t < 64) {
        w0[t] *= extra[0];
        dexpv[t] = __expf(cum[t]);
    }
    __syncthreads();

    {
        const float* rowPtr[16];
        #pragma unroll
        for (int ii=0; ii<16; ii++) {
            int i = g + 4*ii;
            rowPtr[ii] = (i==0) ? w0 : &RK[(i-1)*RKS];
        }
        const float* rowk = (lj==0) ? w0 : &RK[(lj-1)*RKS];
        float acc[16];
        #pragma unroll
        for (int ii=0; ii<16; ii++) acc[ii]=0.f;
        for (int m=0;m<64;m++){
            float wkm = rowk[m];
            #pragma unroll
            for (int ii=0; ii<16; ii++) acc[ii] += rowPtr[ii][m]*wkm;
        }
        #pragma unroll
        for (int ii=0; ii<16; ii++){
            int i = g + 4*ii;
            Mb[i*64 + lj] = (lj < i) ? (-betav[i]*__expf(cum[i]-cum[lj])*acc[ii]) : 0.f;
        }
    }
    __syncthreads();

    for (int idx=t; idx<4096; idx+=256)
        Am[idx] = ((idx>>6)==(idx&63)) ? 1.f : 0.f;
    __syncthreads();
    for (int k=0;k<63;k++){
        for (int i=k+1+g; i<64; i+=4)
            Am[i*64+lj] += Mb[i*64+k]*Am[k*64+lj];
        __syncthreads();
    }

    {
        const float* rowPtr[16];
        #pragma unroll
        for (int ii=0; ii<16; ii++) rowPtr[ii] = &RK[(g+4*ii)*RKS];
        const float* rowj = (lj==0) ? w0 : &RK[(lj-1)*RKS];
        float acc[16];
        #pragma unroll
        for (int ii=0; ii<16; ii++) acc[ii]=0.f;
        for (int m=0;m<64;m++){
            float wjm = rowj[m];
            #pragma unroll
            for (int ii=0; ii<16; ii++) acc[ii] += rowPtr[ii][m]*wjm;
        }
        #pragma unroll
        for (int ii=0; ii<16; ii++){
            int i = g + 4*ii;
            g_intra[base + i*64 + lj] = (i >= lj) ? (__expf(cum[i]-cum[lj])*acc[ii]) : 0.f;
        }
    }
    float cum63 = cum[63];
    for (int idx=t; idx<4096; idx+=256){
        int c = idx>>6, j = idx&63;
        g_rkd[base+idx] = RK[c*RKS+j]*dexpv[c];
        // transposed wkdw: idx = jt*64 + ct  ->  [d][token]
        int jt = idx>>6, ct = idx&63;
        float wcj = (ct==0) ? w0[jt] : RK[(ct-1)*RKS+jt];
        g_wkdw[base+idx] = wcj*__expf(cum63 - cum[ct]);
    }
    if (t==0) g_elast[cid] = __expf(cum63);

    for (int idx=t; idx<4096; idx+=256){
        int c = idx>>6, j = idx&63;
        Mb[c*64+j] = g_v[xbase + (size_t)c*D_ + j]*betav[c];
    }
    __syncthreads();

    {
        float accv[16], accw[16];
        #pragma unroll
        for (int ii=0; ii<16; ii++){ accv[ii]=0.f; accw[ii]=0.f; }
        for (int k=0;k<64;k++){
            float vs = Mb[k*64 + lj];
            float wkv = ((k==0) ? w0[lj] : RK[(k-1)*RKS+lj]) * betav[k]*dexpv[k];
            #pragma unroll
            for (int ii=0; ii<16; ii++){
                float a = Am[(g+4*ii)*64 + k];
                accv[ii] += a*vs;
                accw[ii] += a*wkv;
            }
        }
        #pragma unroll
        for (int ii=0; ii<16; ii++){
            int i = g + 4*ii;
            g_vc[base + i*64 + lj]   = accv[ii];
            g_wkcd[base + i*64 + lj] = accw[ii];
        }
    }
}

// ================= scan: cluster of 2, split e-dim, k-vectorized =================
#define SS 36
#define TS 68
#define SCAN_SMEM ((3*64*SS + 4*64*TS + 64 + 32)*4)

__global__ __launch_bounds__(256) __cluster_dims__(2,1,1) void scan_kernel()
{
    extern __shared__ float sm[];
    float* S     = sm;               // [64][SS]
    float* VN    = S + 64*SS;
    float* VC    = VN + 64*SS;
    float* WKCD  = VC + 64*SS;       // [64][TS]
    float* RKD   = WKCD + 64*TS;
    float* INTRA = RKD + 64*TS;
    float* WKDW  = INTRA + 64*TS;    // [64][TS]  (transposed: [d][k])
    float* gatev = WKDW + 64*TS;
    float* misc  = gatev + 64;

    int bid = blockIdx.x;
    int bh = bid >> 1, half = bid & 1;
    int b = bh >> 4, h = bh & 15;
    int t = threadIdx.x;
    int lane = t & 31, w = t >> 5;
    int ebl = (t & 7) * 4;
    int cbl = (t >> 3) * 2;

    uint32_t exch_addr = smem_u32(&misc[10]);
    uint32_t peer = half ^ 1;

    for (int i=t; i<64*SS; i+=256) S[i]=0.f;
    __syncthreads();

    for (int n=0; n<64; n++){
        size_t gb = ((size_t)bh*64 + n)*4096;
        #pragma unroll
        for (int u=0; u<4; u++){
            int q = u*256 + t;
            int c = q >> 4, jv = (q & 15)*4;
            int so = c*TS + jv;
            *(float4*)&WKCD[so]  = *(const float4*)&g_wkcd[gb + c*64 + jv];
            *(float4*)&RKD[so]   = *(const float4*)&g_rkd[gb + c*64 + jv];
            *(float4*)&INTRA[so] = *(const float4*)&g_intra[gb + c*64 + jv];
            *(float4*)&WKDW[so]  = *(const float4*)&g_wkdw[gb + c*64 + jv];
        }
        #pragma unroll
        for (int u=0; u<2; u++){
            int q = u*256 + t;
            int c = q >> 3, jv = (q & 7)*4;
            *(float4*)&VC[c*SS + jv] = *(const float4*)&g_vc[gb + c*64 + half*32 + jv];
        }
        if (t < 64) gatev[t] = g_gate[((size_t)b*T_ + n*64 + t)*H_ + h];
        if (t == 0) misc[8] = g_elast[bh*64 + n];
        __syncthreads();

        // v_new = vc - wkcd @ S   (k-vectorized)
        {
            float acc[2][4];
            #pragma unroll
            for (int ci=0;ci<2;ci++){
                float4 v = *(float4*)&VC[(cbl+ci)*SS + ebl];
                acc[ci][0]=v.x; acc[ci][1]=v.y; acc[ci][2]=v.z; acc[ci][3]=v.w;
            }
            #pragma unroll 4
            for (int k4=0;k4<64;k4+=4){
                float4 s0 = *(float4*)&S[(k4+0)*SS + ebl];
                float4 s1 = *(float4*)&S[(k4+1)*SS + ebl];
                float4 s2 = *(float4*)&S[(k4+2)*SS + ebl];
                float4 s3 = *(float4*)&S[(k4+3)*SS + ebl];
                #pragma unroll
                for (int ci=0;ci<2;ci++){
                    float4 wv = *(float4*)&WKCD[(cbl+ci)*TS + k4];
                    acc[ci][0] -= wv.x*s0.x + wv.y*s1.x + wv.z*s2.x + wv.w*s3.x;
                    acc[ci][1] -= wv.x*s0.y + wv.y*s1.y + wv.z*s2.y + wv.w*s3.y;
                    acc[ci][2] -= wv.x*s0.z + wv.y*s1.z + wv.z*s2.z + wv.w*s3.z;
                    acc[ci][3] -= wv.x*s0.w + wv.y*s1.w + wv.z*s2.w + wv.w*s3.w;
                }
            }
            #pragma unroll
            for (int ci=0;ci<2;ci++)
                *(float4*)&VN[(cbl+ci)*SS + ebl] =
                    make_float4(acc[ci][0],acc[ci][1],acc[ci][2],acc[ci][3]);
        }
        __syncthreads();

        // o = rkd@S + intra@v_new ; upd = wkdw_T @ v_new
        float upd[2][4];
        {
            float oa[2][4];
            #pragma unroll
            for (int ci=0;ci<2;ci++)
                #pragma unroll
                for (int ei=0;ei<4;ei++){ oa[ci][ei]=0.f; upd[ci][ei]=0.f; }
            #pragma unroll 4
            for (int k4=0;k4<64;k4+=4){
                float4 s0 = *(float4*)&S[(k4+0)*SS + ebl];
                float4 s1 = *(float4*)&S[(k4+1)*SS + ebl];
                float4 s2 = *(float4*)&S[(k4+2)*SS + ebl];
                float4 s3 = *(float4*)&S[(k4+3)*SS + ebl];
                #pragma unroll
                for (int ci=0;ci<2;ci++){
                    float4 wv = *(float4*)&RKD[(cbl+ci)*TS + k4];
                    oa[ci][0] += wv.x*s0.x + wv.y*s1.x + wv.z*s2.x + wv.w*s3.x;
                    oa[ci][1] += wv.x*s0.y + wv.y*s1.y + wv.z*s2.y + wv.w*s3.y;
                    oa[ci][2] += wv.x*s0.z + wv.y*s1.z + wv.z*s2.z + wv.w*s3.z;
                    oa[ci][3] += wv.x*s0.w + wv.y*s1.w + wv.z*s2.w + wv.w*s3.w;
                }
            }
            #pragma unroll 4
            for (int k4=0;k4<64;k4+=4){
                float4 v0 = *(float4*)&VN[(k4+0)*SS + ebl];
                float4 v1 = *(float4*)&VN[(k4+1)*SS + ebl];
                float4 v2 = *(float4*)&VN[(k4+2)*SS + ebl];
                float4 v3 = *(float4*)&VN[(k4+3)*SS + ebl];
                #pragma unroll
                for (int ci=0;ci<2;ci++){
                    float4 wv = *(float4*)&INTRA[(cbl+ci)*TS + k4];
                    oa[ci][0] += wv.x*v0.x + wv.y*v1.x + wv.z*v2.x + wv.w*v3.x;
                    oa[ci][1] += wv.x*v0.y + wv.y*v1.y + wv.z*v2.y + wv.w*v3.y;
                    oa[ci][2] += wv.x*v0.z + wv.y*v1.z + wv.z*v2.z + wv.w*v3.z;
                    oa[ci][3] += wv.x*v0.w + wv.y*v1.w + wv.z*v2.w + wv.w*v3.w;
                }
                #pragma unroll
                for (int di=0;di<2;di++){
                    float4 wd = *(float4*)&WKDW[(cbl+di)*TS + k4];
                    upd[di][0] += wd.x*v0.x + wd.y*v1.x + wd.z*v2.x + wd.w*v3.x;
                    upd[di][1] += wd.x*v0.y + wd.y*v1.y + wd.z*v2.y + wd.w*v3.y;
                    upd[di][2] += wd.x*v0.z + wd.y*v1.z + wd.z*v2.z + wd.w*v3.z;
                    upd[di][3] += wd.x*v0.w + wd.y*v1.w + wd.z*v2.w + wd.w*v3.w;
                }
            }
            #pragma unroll
            for (int ci=0;ci<2;ci++){
                float gt = gatev[cbl+ci];
                size_t orow = ((size_t)b*T_ + n*64 + cbl+ci)*D_ + (size_t)h*64 + half*32 + ebl;
                *(float4*)&g_og[orow] = make_float4(oa[ci][0]*gt, oa[ci][1]*gt,
                                                    oa[ci][2]*gt, oa[ci][3]*gt);
            }
        }
        __syncthreads();

        float el = misc[8];
        float partial = 0.f;
        #pragma unroll
        for (int di=0;di<2;di++){
            #pragma unroll
            for (int ei=0;ei<4;ei++){
                int idx = (cbl+di)*SS + ebl + ei;
                float sv = S[idx]*el + upd[di][ei];
                S[idx] = sv;
                partial += sv*sv;
            }
        }
        #pragma unroll
        for (int off=16; off>0; off>>=1) partial += __shfl_down_sync(0xffffffffu, partial, off);
        if (lane==0) misc[w] = partial;
        __syncthreads();
        if (t==0){
            float s=0.f;
            #pragma unroll
            for (int i=0;i<8;i++) s += misc[i];
            misc[9] = s;
            uint32_t remote;
            asm volatile("mapa.shared::cluster.u32 %0, %1, %2;" : "=r"(remote)
                         : "r"(exch_addr + (n&1)*4), "r"(peer));
            asm volatile("st.shared::cluster.f32 [%0], %1;" :: "r"(remote), "f"(s) : "memory");
        }
        asm volatile("barrier.cluster.arrive.aligned;" ::: "memory");
        asm volatile("barrier.cluster.wait.aligned;" ::: "memory");
        float total = misc[9] + misc[10 + (n&1)];
        float nrm = sqrtf(total);
        float f = fminf(nrm,100.f)/fmaxf(nrm,1e-6f);
        #pragma unroll
        for (int di=0;di<2;di++)
            #pragma unroll
            for (int ei=0;ei<4;ei++)
                S[(cbl+di)*SS + ebl + ei] *= f;
        __syncthreads();
    }
}

extern "C" void kernel_launch(void* const* d_in, const int* in_sizes, int n_in,
                              void* d_out, int out_size) {
    const float* x      = (const float*)d_in[0];
    const float* w_wr   = (const float*)d_in[1];
    const float* w_gate = (const float*)d_in[2];
    const float* w_out  = (const float*)d_in[3];
    const float* w_beta = (const float*)d_in[4];
    const float* w_alph = (const float*)d_in[5];
    const float* dtb    = (const float*)d_in[6];
    const float* alog   = (const float*)d_in[7];
    float* out = (float*)d_out;

    cudaFuncSetAttribute(proj_kernel, cudaFuncAttributeMaxDynamicSharedMemorySize, PROJ_SMEM);
    cudaFuncSetAttribute(prep_kernel, cudaFuncAttributeMaxDynamicSharedMemorySize, PREP_SMEM);
    cudaFuncSetAttribute(scan_kernel, cudaFuncAttributeMaxDynamicSharedMemorySize, SCAN_SMEM);
    cudaFuncSetAttribute(hgemm,       cudaFuncAttributeMaxDynamicSharedMemorySize, G_SMEM);

    __nv_bfloat16 *xb, *ogb, *wb0, *wb1;
    cudaGetSymbolAddress((void**)&xb,  g_xb);
    cudaGetSymbolAddress((void**)&ogb, g_ogb);
    cudaGetSymbolAddress((void**)&wb0, g_wb0);
    cudaGetSymbolAddress((void**)&wb1, g_wb1);
    float* og; cudaGetSymbolAddress((void**)&og, g_og);
    float* gv; cudaGetSymbolAddress((void**)&gv, g_v);

    proj_kernel<<<128, 256, PROJ_SMEM>>>(x, w_gate, w_beta, w_alph, dtb, alog);
    cvt_kernel<<<(BT_*D_/4 + 255)/256, 256>>>(x, xb, BT_*D_/4);
    cvt_kernel<<<(D_*D_/4 + 255)/256, 256>>>(w_wr, wb0, D_*D_/4);
    cvt_kernel<<<(D_*D_/4 + 255)/256, 256>>>(w_out, wb1, D_*D_/4);
    hgemm<<<dim3(8,128), 256, G_SMEM>>>(xb, wb0, nullptr, gv, 0);
    prep_kernel<<<BHN_, 256, PREP_SMEM>>>(x);
    scan_kernel<<<128, 256, SCAN_SMEM>>>();
    cvt_kernel<<<(BT_*D_/4 + 255)/256, 256>>>(og, ogb, BT_*D_/4);
    hgemm<<<dim3(8,128), 256, G_SMEM>>>(ogb, wb1, x, out, 1);
}

// round 8
// speedup vs baseline: 3.5139x; 1.3654x over previous
#include <cuda_runtime.h>
#include <cuda_bf16.h>
#include <math.h>
#include <stdint.h>

#define B_ 4
#define T_ 4096
#define D_ 1024
#define H_ 16
#define C_ 64
#define N_ 64
#define BT_ (B_*T_)
#define BHN_ (B_*H_*N_)

// ---------- scratch ----------
__device__ float g_v[BT_*D_];
__device__ float g_og[BT_*D_];
__device__ float g_gate[BT_*H_];
__device__ float g_beta[BT_*H_];
__device__ float g_dec[BT_*H_];
__device__ float g_rkd[BHN_*4096];
__device__ float g_wkcd[BHN_*4096];
__device__ float g_vc[BHN_*4096];
__device__ float g_wkdw[BHN_*4096];   // TRANSPOSED: [d][token] per chunk
__device__ float g_intra[BHN_*4096];
__device__ float g_elast[BHN_];
__device__ __nv_bfloat16 g_xb[BT_*D_];
__device__ __nv_bfloat16 g_ogb[BT_*D_];
__device__ __nv_bfloat16 g_wb0[D_*D_];
__device__ __nv_bfloat16 g_wb1[D_*D_];

__device__ __forceinline__ uint32_t smem_u32(const void* p){
    uint32_t a;
    asm("{ .reg .u64 t; cvta.to.shared.u64 t, %1; cvt.u32.u64 %0, t; }" : "=r"(a) : "l"(p));
    return a;
}

// ---------------- fp32 -> bf16 convert ----------------
__global__ __launch_bounds__(256) void cvt_kernel(const float* __restrict__ in,
                                                  __nv_bfloat16* __restrict__ out, int n4)
{
    int i = blockIdx.x*256 + threadIdx.x;
    if (i < n4){
        float4 v = ((const float4*)in)[i];
        __nv_bfloat162 a = __floats2bfloat162_rn(v.x, v.y);
        __nv_bfloat162 b = __floats2bfloat162_rn(v.z, v.w);
        ((__nv_bfloat162*)out)[2*i]   = a;
        ((__nv_bfloat162*)out)[2*i+1] = b;
    }
}

// ================= projections =================
#define XS_STRIDE 132
#define PROJ_SMEM ((128*XS_STRIDE + 128*48)*4)
__global__ __launch_bounds__(256) void proj_kernel(
    const float* __restrict__ x, const float* __restrict__ wg,
    const float* __restrict__ wb, const float* __restrict__ wa,
    const float* __restrict__ dtb, const float* __restrict__ alog)
{
    extern __shared__ float psm[];
    float* Xs = psm;
    float* Ws = psm + 128*XS_STRIDE;
    int t = threadIdx.x;
    int row = t & 127, og = t >> 7;
    int o0 = og*24;
    int r0 = blockIdx.x * 128;

    float acc[24];
    #pragma unroll
    for (int j=0;j<24;j++) acc[j]=0.f;

    for (int k0=0; k0<1024; k0+=128){
        #pragma unroll
        for (int i=0;i<16;i++){
            int f4 = i*256 + t;
            int m = f4 >> 5, kv = (f4 & 31)*4;
            float4 v = *(const float4*)&x[(size_t)(r0+m)*1024 + k0 + kv];
            *(float4*)&Xs[m*XS_STRIDE + kv] = v;
        }
        for (int e = t; e < 128*48; e += 256){
            int kk = e / 48, o = e % 48;
            const float* W = (o<16) ? wg : ((o<32) ? wb : wa);
            Ws[kk*48 + o] = W[(size_t)(k0+kk)*16 + (o & 15)];
        }
        __syncthreads();
        #pragma unroll 4
        for (int kk=0; kk<128; kk++){
            float xv = Xs[row*XS_STRIDE + kk];
            const float* wrow = &Ws[kk*48 + o0];
            #pragma unroll
            for (int j=0;j<24;j+=4){
                float4 w4 = *(const float4*)&wrow[j];
                acc[j]   += xv*w4.x; acc[j+1] += xv*w4.y;
                acc[j+2] += xv*w4.z; acc[j+3] += xv*w4.w;
            }
        }
        __syncthreads();
    }
    int rg = r0 + row;
    #pragma unroll
    for (int j=0;j<24;j++){
        int o = o0 + j;
        int h = o & 15, kind = o >> 4;
        float s = acc[j];
        if (kind==0)      g_gate[rg*16+h] = 1.f/(1.f+__expf(-s));
        else if (kind==1) g_beta[rg*16+h] = 1.f/(1.f+__expf(-s));
        else {
            float v = s + dtb[h];
            float sp = fmaxf(v,0.f) + log1pf(__expf(-fabsf(v)));
            g_dec[rg*16+h] = -__expf(alog[h])*sp;
        }
    }
}

// ================= bf16 mma GEMM, cp.async 4-stage =================
#define GS_A_STRIDE 20
#define GS_B_STRIDE 68
#define GS_A_TILE  (128*GS_A_STRIDE)
#define GS_B_TILE  (32*GS_B_STRIDE)
#define GS_STAGE   (GS_A_TILE + GS_B_TILE)
#define G_SMEM     (4*GS_STAGE*4)

__device__ __forceinline__ void ldsm4(unsigned r[4], uint32_t a){
    asm volatile("ldmatrix.sync.aligned.m8n8.x4.shared.b16 {%0,%1,%2,%3}, [%4];"
        : "=r"(r[0]),"=r"(r[1]),"=r"(r[2]),"=r"(r[3]) : "r"(a));
}
__device__ __forceinline__ void ldsm4t(unsigned r[4], uint32_t a){
    asm volatile("ldmatrix.sync.aligned.m8n8.x4.trans.shared.b16 {%0,%1,%2,%3}, [%4];"
        : "=r"(r[0]),"=r"(r[1]),"=r"(r[2]),"=r"(r[3]) : "r"(a));
}
__device__ __forceinline__ void mma_bf16(float* c, const unsigned* a, unsigned b0, unsigned b1){
    asm volatile("mma.sync.aligned.m16n8k16.row.col.f32.bf16.bf16.f32 "
      "{%0,%1,%2,%3}, {%4,%5,%6,%7}, {%8,%9}, {%0,%1,%2,%3};"
      : "+f"(c[0]),"+f"(c[1]),"+f"(c[2]),"+f"(c[3])
      : "r"(a[0]),"r"(a[1]),"r"(a[2]),"r"(a[3]),"r"(b0),"r"(b1));
}

__global__ __launch_bounds__(256) void hgemm(
    const __nv_bfloat16* __restrict__ A, const __nv_bfloat16* __restrict__ Bw,
    const float* __restrict__ R, float* __restrict__ C, int mode)
{
    extern __shared__ float gsm[];
    uint32_t sbase = smem_u32(gsm);

    int t = threadIdx.x, lane = t & 31, warp = t >> 5;
    int wm = warp >> 1, wn = warp & 1;
    int bm = blockIdx.y, bn = blockIdx.x;
    const __nv_bfloat16* Ab = A + (size_t)(bm*128)*1024;
    const __nv_bfloat16* Bb = Bw + (size_t)bn*128;

    float acc[2][8][4];
    #pragma unroll
    for (int mt=0;mt<2;mt++)
        #pragma unroll
        for (int j=0;j<8;j++)
            #pragma unroll
            for (int r=0;r<4;r++) acc[mt][j][r]=0.f;

    auto issue = [&](int it){
        uint32_t st = sbase + (uint32_t)(it & 3)*(GS_STAGE*4);
        #pragma unroll
        for (int u=0;u<2;u++){
            int row = u*64 + (t>>2), ch = t&3;
            uint32_t so = st + (uint32_t)((row*GS_A_STRIDE + ch*4)*4);
            const __nv_bfloat16* gp = Ab + (size_t)row*1024 + it*32 + ch*8;
            asm volatile("cp.async.cg.shared.global [%0], [%1], 16;" :: "r"(so), "l"(gp));
        }
        uint32_t sb = st + GS_A_TILE*4;
        #pragma unroll
        for (int u=0;u<2;u++){
            int row = u*16 + (t>>4), ch = t&15;
            uint32_t so = sb + (uint32_t)((row*GS_B_STRIDE + ch*4)*4);
            const __nv_bfloat16* gp = Bb + (size_t)(it*32 + row)*1024 + ch*8;
            asm volatile("cp.async.cg.shared.global [%0], [%1], 16;" :: "r"(so), "l"(gp));
        }
    };

    issue(0); asm volatile("cp.async.commit_group;" ::: "memory");
    issue(1); asm volatile("cp.async.commit_group;" ::: "memory");
    issue(2); asm volatile("cp.async.commit_group;" ::: "memory");

    for (int it=0; it<32; it++){
        asm volatile("cp.async.wait_group 2;" ::: "memory");
        __syncthreads();
        if (it+3 < 32){
            issue(it+3);
            asm volatile("cp.async.commit_group;" ::: "memory");
        }
        uint32_t sa = sbase + (uint32_t)(it & 3)*(GS_STAGE*4);
        uint32_t sb = sa + GS_A_TILE*4;
        #pragma unroll
        for (int s=0;s<2;s++){
            unsigned af[2][4], bfr[4][4];
            #pragma unroll
            for (int mt=0;mt<2;mt++){
                uint32_t ad = sa + (uint32_t)((((wm*32 + mt*16 + (lane&15))*GS_A_STRIDE)
                                  + s*8 + ((lane>>4)&1)*4)*4);
                ldsm4(af[mt], ad);
            }
            #pragma unroll
            for (int nt=0;nt<4;nt++){
                uint32_t bd = sb + (uint32_t)((((s*16 + (lane&7) + ((lane>>3)&1)*8)*GS_B_STRIDE)
                                  + wn*32 + nt*8 + ((lane>>4)&1)*4)*4);
                ldsm4t(bfr[nt], bd);
            }
            #pragma unroll
            for (int mt=0;mt<2;mt++)
                #pragma unroll
                for (int j=0;j<8;j++)
                    mma_bf16(acc[mt][j], af[mt], bfr[j>>1][(j&1)*2], bfr[j>>1][(j&1)*2+1]);
        }
    }

    int g = lane >> 2, tg = lane & 3;
    #pragma unroll
    for (int mt=0; mt<2; mt++){
        int r0 = bm*128 + wm*32 + mt*16 + g;
        #pragma unroll
        for (int j=0; j<8; j++){
            int col = bn*128 + wn*64 + j*8 + tg*2;
            size_t o0 = (size_t)r0*1024 + col;
            size_t o1 = o0 + (size_t)8*1024;
            float2 v0 = make_float2(acc[mt][j][0], acc[mt][j][1]);
            float2 v1 = make_float2(acc[mt][j][2], acc[mt][j][3]);
            if (mode){
                float2 q0 = *(const float2*)&R[o0];
                float2 q1 = *(const float2*)&R[o1];
                v0.x += q0.x; v0.y += q0.y; v1.x += q1.x; v1.y += q1.y;
            }
            *(float2*)&C[o0] = v0;
            *(float2*)&C[o1] = v1;
        }
    }
}

// ================= per-chunk prep (rewritten) =================
// WK rows 0..64: normalized keys of tokens n*64-1 .. n*64+63 (row 0 = zeros for n==0)
//   rk_i = WK[i+1], wk_i = WK[i]
// G'[r][c] = dot(WK[r+1], WK[c])  -> serves Bm (G'[i-1][j]) and intra (G'[i][j])
// Y (128 cols): [v*beta | wk*beta*dexp], forward-substituted in registers.
#define WKS 68
#define PREP_SMEM ((65*WKS + 4096 + 4096 + 64*3 + 8)*4)

__global__ __launch_bounds__(256) void prep_kernel(const float* __restrict__ x)
{
    extern __shared__ float sm[];
    float* WK    = sm;              // 65*WKS
    float* Gm    = WK + 65*WKS;     // 4096: VS stage, then G'
    float* Mb    = Gm + 4096;       // 4096: Bm
    float* cum   = Mb + 4096;       // 64
    float* dexpv = cum + 64;        // 64
    float* betav = dexpv + 64;      // 64

    int cid = blockIdx.x;
    int b = cid / (H_*N_);
    int h = (cid / N_) % H_;
    int n = cid % N_;
    int t = threadIdx.x;
    size_t xbase = ((size_t)b*T_ + (size_t)n*C_)*D_ + (size_t)h*64;
    size_t base  = (size_t)cid*4096;

    // 1. load 65 key rows + beta/decay
    for (int f = t; f < 65*16; f += 256){
        int r = f >> 4, j4 = (f & 15)*4;
        float4 v;
        if (r == 0 && n == 0) v = make_float4(0.f,0.f,0.f,0.f);
        else v = *(const float4*)&x[xbase + ((size_t)r-1)*D_ + j4];
        *(float4*)&WK[r*WKS + j4] = v;
    }
    if (t < 64){
        int tok = (b*T_ + n*C_ + t)*H_ + h;
        betav[t] = g_beta[tok];
        cum[t]   = g_dec[tok];
    }
    __syncthreads();

    // 2. normalize rows; cumsum
    if (t < 65){
        float s = 0.f;
        #pragma unroll
        for (int q=0;q<16;q++){
            float4 v = *(float4*)&WK[t*WKS + q*4];
            s += v.x*v.x + v.y*v.y + v.z*v.z + v.w*v.w;
        }
        float inv = 1.f/fmaxf(sqrtf(s), 1e-12f);
        #pragma unroll
        for (int q=0;q<16;q++){
            float4 v = *(float4*)&WK[t*WKS + q*4];
            v.x*=inv; v.y*=inv; v.z*=inv; v.w*=inv;
            *(float4*)&WK[t*WKS + q*4] = v;
        }
    }
    if (t == 65){
        float s = 0.f;
        for (int c=0;c<64;c++){ s += cum[c]; cum[c] = s; }
    }
    __syncthreads();
    if (t < 64) dexpv[t] = __expf(cum[t]);

    // 3. VS stage into Gm
    for (int f = t; f < 1024; f += 256){
        int i = f >> 4, j4 = (f & 15)*4;
        float4 v = *(const float4*)&g_v[xbase + (size_t)i*D_ + j4];
        float bt = betav[i];
        v.x*=bt; v.y*=bt; v.z*=bt; v.w*=bt;
        *(float4*)&Gm[i*64 + j4] = v;
    }
    __syncthreads();

    // 4. Y extract (threads 0-127): column-in-registers
    float y[64];
    if (t < 128){
        if (t < 64){
            #pragma unroll
            for (int i=0;i<64;i++) y[i] = Gm[i*64 + t];
        } else {
            int jj = t - 64;
            #pragma unroll
            for (int i=0;i<64;i++) y[i] = WK[i*WKS + jj]*betav[i]*dexpv[i];
        }
    }
    __syncthreads();

    // 5. G' gemm into Gm (4x4 register blocks, float4 over m)
    {
        int tr = (t >> 4)*4, tc = (t & 15)*4;
        float d[4][4];
        #pragma unroll
        for (int a=0;a<4;a++)
            #pragma unroll
            for (int c=0;c<4;c++) d[a][c]=0.f;
        for (int m4=0; m4<64; m4+=4){
            float4 av[4], cv[4];
            #pragma unroll
            for (int a=0;a<4;a++) av[a] = *(float4*)&WK[(tr+a+1)*WKS + m4];
            #pragma unroll
            for (int c=0;c<4;c++) cv[c] = *(float4*)&WK[(tc+c)*WKS + m4];
            #pragma unroll
            for (int a=0;a<4;a++)
                #pragma unroll
                for (int c=0;c<4;c++)
                    d[a][c] += av[a].x*cv[c].x + av[a].y*cv[c].y
                             + av[a].z*cv[c].z + av[a].w*cv[c].w;
        }
        __syncthreads();   // all VS reads done (already) / WK reads done before overwrite of Gm
        #pragma unroll
        for (int a=0;a<4;a++)
            #pragma unroll
            for (int c=0;c<4;c++)
                Gm[(tr+a)*64 + tc+c] = d[a][c];
    }
    __syncthreads();

    // 6. Bm materialize
    for (int f = t; f < 4096; f += 256){
        int i = f >> 6, j = f & 63;
        Mb[f] = (j < i) ? (-betav[i]*__expf(cum[i]-cum[j])*Gm[(i-1)*64 + j]) : 0.f;
    }
    __syncthreads();

    float cum63 = cum[63];

    // 7. fork: warps 0-3 substitute; warps 4-7 write intra/rkd/wkdw
    if (t < 128){
        #pragma unroll
        for (int k=0;k<63;k++){
            float yk = y[k];
            #pragma unroll
            for (int i=k+1;i<64;i++)
                y[i] = fmaf(Mb[i*64 + k], yk, y[i]);
        }
        if (t < 64){
            #pragma unroll
            for (int i=0;i<64;i++) g_vc[base + i*64 + t] = y[i];
        } else {
            int jj = t - 64;
            #pragma unroll
            for (int i=0;i<64;i++) g_wkcd[base + i*64 + jj] = y[i];
        }
    } else {
        int tt = t - 128;
        // intra[i][j] = (i>=j) ? exp(cum_i-cum_j)*G'[i][j] : 0
        for (int f = tt; f < 4096; f += 128){
            int i = f >> 6, j = f & 63;
            g_intra[base + f] = (i >= j) ? (__expf(cum[i]-cum[j])*Gm[f]) : 0.f;
        }
        // rkd[i][j] = rk_i[j]*dexp_i
        for (int f = tt; f < 1024; f += 128){
            int i = f >> 4, j4 = (f & 15)*4;
            float4 v = *(float4*)&WK[(i+1)*WKS + j4];
            float dv = dexpv[i];
            v.x*=dv; v.y*=dv; v.z*=dv; v.w*=dv;
            *(float4*)&g_rkd[base + i*64 + j4] = v;
        }
        // wkdw transposed: [d][token]
        for (int f = tt; f < 4096; f += 128){
            int jt = f >> 6, ct = f & 63;
            g_wkdw[base + f] = WK[ct*WKS + jt]*__expf(cum63 - cum[ct]);
        }
        if (t == 128) g_elast[cid] = __expf(cum63);
    }
}

// ================= scan: cluster of 2, split e-dim, k-vectorized =================
#define SS 36
#define TS 68
#define SCAN_SMEM ((3*64*SS + 4*64*TS + 64 + 32)*4)

__global__ __launch_bounds__(256) __cluster_dims__(2,1,1) void scan_kernel()
{
    extern __shared__ float sm[];
    float* S     = sm;
    float* VN    = S + 64*SS;
    float* VC    = VN + 64*SS;
    float* WKCD  = VC + 64*SS;
    float* RKD   = WKCD + 64*TS;
    float* INTRA = RKD + 64*TS;
    float* WKDW  = INTRA + 64*TS;
    float* gatev = WKDW + 64*TS;
    float* misc  = gatev + 64;

    int bid = blockIdx.x;
    int bh = bid >> 1, half = bid & 1;
    int b = bh >> 4, h = bh & 15;
    int t = threadIdx.x;
    int lane = t & 31, w = t >> 5;
    int ebl = (t & 7) * 4;
    int cbl = (t >> 3) * 2;

    uint32_t exch_addr = smem_u32(&misc[10]);
    uint32_t peer = half ^ 1;

    for (int i=t; i<64*SS; i+=256) S[i]=0.f;
    __syncthreads();

    for (int n=0; n<64; n++){
        size_t gb = ((size_t)bh*64 + n)*4096;
        #pragma unroll
        for (int u=0; u<4; u++){
            int q = u*256 + t;
            int c = q >> 4, jv = (q & 15)*4;
            int so = c*TS + jv;
            *(float4*)&WKCD[so]  = *(const float4*)&g_wkcd[gb + c*64 + jv];
            *(float4*)&RKD[so]   = *(const float4*)&g_rkd[gb + c*64 + jv];
            *(float4*)&INTRA[so] = *(const float4*)&g_intra[gb + c*64 + jv];
            *(float4*)&WKDW[so]  = *(const float4*)&g_wkdw[gb + c*64 + jv];
        }
        #pragma unroll
        for (int u=0; u<2; u++){
            int q = u*256 + t;
            int c = q >> 3, jv = (q & 7)*4;
            *(float4*)&VC[c*SS + jv] = *(const float4*)&g_vc[gb + c*64 + half*32 + jv];
        }
        if (t < 64) gatev[t] = g_gate[((size_t)b*T_ + n*64 + t)*H_ + h];
        if (t == 0) misc[8] = g_elast[bh*64 + n];
        __syncthreads();

        {
            float acc[2][4];
            #pragma unroll
            for (int ci=0;ci<2;ci++){
                float4 v = *(float4*)&VC[(cbl+ci)*SS + ebl];
                acc[ci][0]=v.x; acc[ci][1]=v.y; acc[ci][2]=v.z; acc[ci][3]=v.w;
            }
            #pragma unroll 4
            for (int k4=0;k4<64;k4+=4){
                float4 s0 = *(float4*)&S[(k4+0)*SS + ebl];
                float4 s1 = *(float4*)&S[(k4+1)*SS + ebl];
                float4 s2 = *(float4*)&S[(k4+2)*SS + ebl];
                float4 s3 = *(float4*)&S[(k4+3)*SS + ebl];
                #pragma unroll
                for (int ci=0;ci<2;ci++){
                    float4 wv = *(float4*)&WKCD[(cbl+ci)*TS + k4];
                    acc[ci][0] -= wv.x*s0.x + wv.y*s1.x + wv.z*s2.x + wv.w*s3.x;
                    acc[ci][1] -= wv.x*s0.y + wv.y*s1.y + wv.z*s2.y + wv.w*s3.y;
                    acc[ci][2] -= wv.x*s0.z + wv.y*s1.z + wv.z*s2.z + wv.w*s3.z;
                    acc[ci][3] -= wv.x*s0.w + wv.y*s1.w + wv.z*s2.w + wv.w*s3.w;
                }
            }
            #pragma unroll
            for (int ci=0;ci<2;ci++)
                *(float4*)&VN[(cbl+ci)*SS + ebl] =
                    make_float4(acc[ci][0],acc[ci][1],acc[ci][2],acc[ci][3]);
        }
        __syncthreads();

        float upd[2][4];
        {
            float oa[2][4];
            #pragma unroll
            for (int ci=0;ci<2;ci++)
                #pragma unroll
                for (int ei=0;ei<4;ei++){ oa[ci][ei]=0.f; upd[ci][ei]=0.f; }
            #pragma unroll 4
            for (int k4=0;k4<64;k4+=4){
                float4 s0 = *(float4*)&S[(k4+0)*SS + ebl];
                float4 s1 = *(float4*)&S[(k4+1)*SS + ebl];
                float4 s2 = *(float4*)&S[(k4+2)*SS + ebl];
                float4 s3 = *(float4*)&S[(k4+3)*SS + ebl];
                #pragma unroll
                for (int ci=0;ci<2;ci++){
                    float4 wv = *(float4*)&RKD[(cbl+ci)*TS + k4];
                    oa[ci][0] += wv.x*s0.x + wv.y*s1.x + wv.z*s2.x + wv.w*s3.x;
                    oa[ci][1] += wv.x*s0.y + wv.y*s1.y + wv.z*s2.y + wv.w*s3.y;
                    oa[ci][2] += wv.x*s0.z + wv.y*s1.z + wv.z*s2.z + wv.w*s3.z;
                    oa[ci][3] += wv.x*s0.w + wv.y*s1.w + wv.z*s2.w + wv.w*s3.w;
                }
            }
            #pragma unroll 4
            for (int k4=0;k4<64;k4+=4){
                float4 v0 = *(float4*)&VN[(k4+0)*SS + ebl];
                float4 v1 = *(float4*)&VN[(k4+1)*SS + ebl];
                float4 v2 = *(float4*)&VN[(k4+2)*SS + ebl];
                float4 v3 = *(float4*)&VN[(k4+3)*SS + ebl];
                #pragma unroll
                for (int ci=0;ci<2;ci++){
                    float4 wv = *(float4*)&INTRA[(cbl+ci)*TS + k4];
                    oa[ci][0] += wv.x*v0.x + wv.y*v1.x + wv.z*v2.x + wv.w*v3.x;
                    oa[ci][1] += wv.x*v0.y + wv.y*v1.y + wv.z*v2.y + wv.w*v3.y;
                    oa[ci][2] += wv.x*v0.z + wv.y*v1.z + wv.z*v2.z + wv.w*v3.z;
                    oa[ci][3] += wv.x*v0.w + wv.y*v1.w + wv.z*v2.w + wv.w*v3.w;
                }
                #pragma unroll
                for (int di=0;di<2;di++){
                    float4 wd = *(float4*)&WKDW[(cbl+di)*TS + k4];
                    upd[di][0] += wd.x*v0.x + wd.y*v1.x + wd.z*v2.x + wd.w*v3.x;
                    upd[di][1] += wd.x*v0.y + wd.y*v1.y + wd.z*v2.y + wd.w*v3.y;
                    upd[di][2] += wd.x*v0.z + wd.y*v1.z + wd.z*v2.z + wd.w*v3.z;
                    upd[di][3] += wd.x*v0.w + wd.y*v1.w + wd.z*v2.w + wd.w*v3.w;
                }
            }
            #pragma unroll
            for (int ci=0;ci<2;ci++){
                float gt = gatev[cbl+ci];
                size_t orow = ((size_t)b*T_ + n*64 + cbl+ci)*D_ + (size_t)h*64 + half*32 + ebl;
                *(float4*)&g_og[orow] = make_float4(oa[ci][0]*gt, oa[ci][1]*gt,
                                                    oa[ci][2]*gt, oa[ci][3]*gt);
            }
        }
        __syncthreads();

        float el = misc[8];
        float partial = 0.f;
        #pragma unroll
        for (int di=0;di<2;di++){
            #pragma unroll
            for (int ei=0;ei<4;ei++){
                int idx = (cbl+di)*SS + ebl + ei;
                float sv = S[idx]*el + upd[di][ei];
                S[idx] = sv;
                partial += sv*sv;
            }
        }
        #pragma unroll
        for (int off=16; off>0; off>>=1) partial += __shfl_down_sync(0xffffffffu, partial, off);
        if (lane==0) misc[w] = partial;
        __syncthreads();
        if (t==0){
            float s=0.f;
            #pragma unroll
            for (int i=0;i<8;i++) s += misc[i];
            misc[9] = s;
            uint32_t remote;
            asm volatile("mapa.shared::cluster.u32 %0, %1, %2;" : "=r"(remote)
                         : "r"(exch_addr + (n&1)*4), "r"(peer));
            asm volatile("st.shared::cluster.f32 [%0], %1;" :: "r"(remote), "f"(s) : "memory");
        }
        asm volatile("barrier.cluster.arrive.aligned;" ::: "memory");
        asm volatile("barrier.cluster.wait.aligned;" ::: "memory");
        float total = misc[9] + misc[10 + (n&1)];
        float nrm = sqrtf(total);
        float f = fminf(nrm,100.f)/fmaxf(nrm,1e-6f);
        #pragma unroll
        for (int di=0;di<2;di++)
            #pragma unroll
            for (int ei=0;ei<4;ei++)
                S[(cbl+di)*SS + ebl + ei] *= f;
        __syncthreads();
    }
}

extern "C" void kernel_launch(void* const* d_in, const int* in_sizes, int n_in,
                              void* d_out, int out_size) {
    const float* x      = (const float*)d_in[0];
    const float* w_wr   = (const float*)d_in[1];
    const float* w_gate = (const float*)d_in[2];
    const float* w_out  = (const float*)d_in[3];
    const float* w_beta = (const float*)d_in[4];
    const float* w_alph = (const float*)d_in[5];
    const float* dtb    = (const float*)d_in[6];
    const float* alog   = (const float*)d_in[7];
    float* out = (float*)d_out;

    cudaFuncSetAttribute(proj_kernel, cudaFuncAttributeMaxDynamicSharedMemorySize, PROJ_SMEM);
    cudaFuncSetAttribute(prep_kernel, cudaFuncAttributeMaxDynamicSharedMemorySize, PREP_SMEM);
    cudaFuncSetAttribute(scan_kernel, cudaFuncAttributeMaxDynamicSharedMemorySize, SCAN_SMEM);
    cudaFuncSetAttribute(hgemm,       cudaFuncAttributeMaxDynamicSharedMemorySize, G_SMEM);

    __nv_bfloat16 *xb, *ogb, *wb0, *wb1;
    cudaGetSymbolAddress((void**)&xb,  g_xb);
    cudaGetSymbolAddress((void**)&ogb, g_ogb);
    cudaGetSymbolAddress((void**)&wb0, g_wb0);
    cudaGetSymbolAddress((void**)&wb1, g_wb1);
    float* og; cudaGetSymbolAddress((void**)&og, g_og);
    float* gv; cudaGetSymbolAddress((void**)&gv, g_v);

    proj_kernel<<<128, 256, PROJ_SMEM>>>(x, w_gate, w_beta, w_alph, dtb, alog);
    cvt_kernel<<<(BT_*D_/4 + 255)/256, 256>>>(x, xb, BT_*D_/4);
    cvt_kernel<<<(D_*D_/4 + 255)/256, 256>>>(w_wr, wb0, D_*D_/4);
    cvt_kernel<<<(D_*D_/4 + 255)/256, 256>>>(w_out, wb1, D_*D_/4);
    hgemm<<<dim3(8,128), 256, G_SMEM>>>(xb, wb0, nullptr, gv, 0);
    prep_kernel<<<BHN_, 256, PREP_SMEM>>>(x);
    scan_kernel<<<128, 256, SCAN_SMEM>>>();
    cvt_kernel<<<(BT_*D_/4 + 255)/256, 256>>>(og, ogb, BT_*D_/4);
    hgemm<<<dim3(8,128), 256, G_SMEM>>>(ogb, wb1, x, out, 1);
}

// round 9
// speedup vs baseline: 3.6718x; 1.0449x over previous
#include <cuda_runtime.h>
#include <cuda_bf16.h>
#include <math.h>
#include <stdint.h>

#define B_ 4
#define T_ 4096
#define D_ 1024
#define H_ 16
#define C_ 64
#define N_ 64
#define BT_ (B_*T_)
#define BHN_ (B_*H_*N_)

typedef unsigned long long u64;
struct alignas(16) u64x2 { u64 a, b; };

// ---------- scratch ----------
__device__ float g_v[BT_*D_];
__device__ float g_gate[BT_*H_];
__device__ float g_beta[BT_*H_];
__device__ float g_dec[BT_*H_];
__device__ float g_rkd[BHN_*4096];
__device__ float g_wkcd[BHN_*4096];   // NEGATED (scan adds)
__device__ float g_vc[BHN_*4096];
__device__ float g_wkdw[BHN_*4096];   // TRANSPOSED: [d][token]
__device__ float g_intra[BHN_*4096];
__device__ float g_elast[BHN_];
__device__ __nv_bfloat16 g_xb[BT_*D_];
__device__ __nv_bfloat16 g_ogb[BT_*D_];   // gated output (bf16, written by scan)
__device__ __nv_bfloat16 g_wb0[D_*D_];
__device__ __nv_bfloat16 g_wb1[D_*D_];

__device__ __forceinline__ uint32_t smem_u32(const void* p){
    uint32_t a;
    asm("{ .reg .u64 t; cvta.to.shared.u64 t, %1; cvt.u32.u64 %0, t; }" : "=r"(a) : "l"(p));
    return a;
}
__device__ __forceinline__ u64 pk2(float x){
    u64 r; asm("mov.b64 %0, {%1,%1};" : "=l"(r) : "f"(x)); return r;
}
__device__ __forceinline__ void fma2(u64& d, u64 a, u64 b){
    asm("fma.rn.f32x2 %0, %1, %2, %0;" : "+l"(d) : "l"(a), "l"(b));
}
__device__ __forceinline__ float2 up2(u64 v){
    float2 f; asm("mov.b64 {%0,%1}, %2;" : "=f"(f.x), "=f"(f.y) : "l"(v)); return f;
}

// ---------------- fp32 -> bf16 convert ----------------
__global__ __launch_bounds__(256) void cvt_kernel(const float* __restrict__ in,
                                                  __nv_bfloat16* __restrict__ out, int n4)
{
    int i = blockIdx.x*256 + threadIdx.x;
    if (i < n4){
        float4 v = ((const float4*)in)[i];
        __nv_bfloat162 a = __floats2bfloat162_rn(v.x, v.y);
        __nv_bfloat162 b = __floats2bfloat162_rn(v.z, v.w);
        ((__nv_bfloat162*)out)[2*i]   = a;
        ((__nv_bfloat162*)out)[2*i+1] = b;
    }
}

// ================= projections =================
#define XS_STRIDE 132
#define PROJ_SMEM ((128*XS_STRIDE + 128*48)*4)
__global__ __launch_bounds__(256) void proj_kernel(
    const float* __restrict__ x, const float* __restrict__ wg,
    const float* __restrict__ wb, const float* __restrict__ wa,
    const float* __restrict__ dtb, const float* __restrict__ alog)
{
    extern __shared__ float psm[];
    float* Xs = psm;
    float* Ws = psm + 128*XS_STRIDE;
    int t = threadIdx.x;
    int row = t & 127, og = t >> 7;
    int o0 = og*24;
    int r0 = blockIdx.x * 128;

    float acc[24];
    #pragma unroll
    for (int j=0;j<24;j++) acc[j]=0.f;

    for (int k0=0; k0<1024; k0+=128){
        #pragma unroll
        for (int i=0;i<16;i++){
            int f4 = i*256 + t;
            int m = f4 >> 5, kv = (f4 & 31)*4;
            float4 v = *(const float4*)&x[(size_t)(r0+m)*1024 + k0 + kv];
            *(float4*)&Xs[m*XS_STRIDE + kv] = v;
        }
        for (int e = t; e < 128*48; e += 256){
            int kk = e / 48, o = e % 48;
            const float* W = (o<16) ? wg : ((o<32) ? wb : wa);
            Ws[kk*48 + o] = W[(size_t)(k0+kk)*16 + (o & 15)];
        }
        __syncthreads();
        #pragma unroll 4
        for (int kk=0; kk<128; kk++){
            float xv = Xs[row*XS_STRIDE + kk];
            const float* wrow = &Ws[kk*48 + o0];
            #pragma unroll
            for (int j=0;j<24;j+=4){
                float4 w4 = *(const float4*)&wrow[j];
                acc[j]   += xv*w4.x; acc[j+1] += xv*w4.y;
                acc[j+2] += xv*w4.z; acc[j+3] += xv*w4.w;
            }
        }
        __syncthreads();
    }
    int rg = r0 + row;
    #pragma unroll
    for (int j=0;j<24;j++){
        int o = o0 + j;
        int h = o & 15, kind = o >> 4;
        float s = acc[j];
        if (kind==0)      g_gate[rg*16+h] = 1.f/(1.f+__expf(-s));
        else if (kind==1) g_beta[rg*16+h] = 1.f/(1.f+__expf(-s));
        else {
            float v = s + dtb[h];
            float sp = fmaxf(v,0.f) + log1pf(__expf(-fabsf(v)));
            g_dec[rg*16+h] = -__expf(alog[h])*sp;
        }
    }
}

// ================= bf16 mma GEMM, cp.async 3-stage, 2 CTAs/SM =================
#define GS_A_STRIDE 20
#define GS_B_STRIDE 68
#define GS_A_TILE  (128*GS_A_STRIDE)
#define GS_B_TILE  (32*GS_B_STRIDE)
#define GS_STAGE   (GS_A_TILE + GS_B_TILE)
#define G_SMEM     (3*GS_STAGE*4)

__device__ __forceinline__ void ldsm4(unsigned r[4], uint32_t a){
    asm volatile("ldmatrix.sync.aligned.m8n8.x4.shared.b16 {%0,%1,%2,%3}, [%4];"
        : "=r"(r[0]),"=r"(r[1]),"=r"(r[2]),"=r"(r[3]) : "r"(a));
}
__device__ __forceinline__ void ldsm4t(unsigned r[4], uint32_t a){
    asm volatile("ldmatrix.sync.aligned.m8n8.x4.trans.shared.b16 {%0,%1,%2,%3}, [%4];"
        : "=r"(r[0]),"=r"(r[1]),"=r"(r[2]),"=r"(r[3]) : "r"(a));
}
__device__ __forceinline__ void mma_bf16(float* c, const unsigned* a, unsigned b0, unsigned b1){
    asm volatile("mma.sync.aligned.m16n8k16.row.col.f32.bf16.bf16.f32 "
      "{%0,%1,%2,%3}, {%4,%5,%6,%7}, {%8,%9}, {%0,%1,%2,%3};"
      : "+f"(c[0]),"+f"(c[1]),"+f"(c[2]),"+f"(c[3])
      : "r"(a[0]),"r"(a[1]),"r"(a[2]),"r"(a[3]),"r"(b0),"r"(b1));
}

__global__ __launch_bounds__(256) void hgemm(
    const __nv_bfloat16* __restrict__ A, const __nv_bfloat16* __restrict__ Bw,
    const float* __restrict__ R, float* __restrict__ C, int mode)
{
    extern __shared__ float gsm[];
    uint32_t sbase = smem_u32(gsm);

    int t = threadIdx.x, lane = t & 31, warp = t >> 5;
    int wm = warp >> 1, wn = warp & 1;
    int bm = blockIdx.y, bn = blockIdx.x;
    const __nv_bfloat16* Ab = A + (size_t)(bm*128)*1024;
    const __nv_bfloat16* Bb = Bw + (size_t)bn*128;

    float acc[2][8][4];
    #pragma unroll
    for (int mt=0;mt<2;mt++)
        #pragma unroll
        for (int j=0;j<8;j++)
            #pragma unroll
            for (int r=0;r<4;r++) acc[mt][j][r]=0.f;

    auto issue = [&](int it){
        uint32_t st = sbase + (uint32_t)(it % 3)*(GS_STAGE*4);
        #pragma unroll
        for (int u=0;u<2;u++){
            int row = u*64 + (t>>2), ch = t&3;
            uint32_t so = st + (uint32_t)((row*GS_A_STRIDE + ch*4)*4);
            const __nv_bfloat16* gp = Ab + (size_t)row*1024 + it*32 + ch*8;
            asm volatile("cp.async.cg.shared.global [%0], [%1], 16;" :: "r"(so), "l"(gp));
        }
        uint32_t sb = st + GS_A_TILE*4;
        #pragma unroll
        for (int u=0;u<2;u++){
            int row = u*16 + (t>>4), ch = t&15;
            uint32_t so = sb + (uint32_t)((row*GS_B_STRIDE + ch*4)*4);
            const __nv_bfloat16* gp = Bb + (size_t)(it*32 + row)*1024 + ch*8;
            asm volatile("cp.async.cg.shared.global [%0], [%1], 16;" :: "r"(so), "l"(gp));
        }
    };

    issue(0); asm volatile("cp.async.commit_group;" ::: "memory");
    issue(1); asm volatile("cp.async.commit_group;" ::: "memory");

    for (int it=0; it<32; it++){
        if (it < 31) asm volatile("cp.async.wait_group 1;" ::: "memory");
        else         asm volatile("cp.async.wait_group 0;" ::: "memory");
        __syncthreads();
        if (it+2 < 32){
            issue(it+2);
            asm volatile("cp.async.commit_group;" ::: "memory");
        }
        uint32_t sa = sbase + (uint32_t)(it % 3)*(GS_STAGE*4);
        uint32_t sb = sa + GS_A_TILE*4;
        #pragma unroll
        for (int s=0;s<2;s++){
            unsigned af[2][4], bfr[4][4];
            #pragma unroll
            for (int mt=0;mt<2;mt++){
                uint32_t ad = sa + (uint32_t)((((wm*32 + mt*16 + (lane&15))*GS_A_STRIDE)
                                  + s*8 + ((lane>>4)&1)*4)*4);
                ldsm4(af[mt], ad);
            }
            #pragma unroll
            for (int nt=0;nt<4;nt++){
                uint32_t bd = sb + (uint32_t)((((s*16 + (lane&7) + ((lane>>3)&1)*8)*GS_B_STRIDE)
                                  + wn*32 + nt*8 + ((lane>>4)&1)*4)*4);
                ldsm4t(bfr[nt], bd);
            }
            #pragma unroll
            for (int mt=0;mt<2;mt++)
                #pragma unroll
                for (int j=0;j<8;j++)
                    mma_bf16(acc[mt][j], af[mt], bfr[j>>1][(j&1)*2], bfr[j>>1][(j&1)*2+1]);
        }
    }

    int g = lane >> 2, tg = lane & 3;
    #pragma unroll
    for (int mt=0; mt<2; mt++){
        int r0 = bm*128 + wm*32 + mt*16 + g;
        #pragma unroll
        for (int j=0; j<8; j++){
            int col = bn*128 + wn*64 + j*8 + tg*2;
            size_t o0 = (size_t)r0*1024 + col;
            size_t o1 = o0 + (size_t)8*1024;
            float2 v0 = make_float2(acc[mt][j][0], acc[mt][j][1]);
            float2 v1 = make_float2(acc[mt][j][2], acc[mt][j][3]);
            if (mode){
                float2 q0 = *(const float2*)&R[o0];
                float2 q1 = *(const float2*)&R[o1];
                v0.x += q0.x; v0.y += q0.y; v1.x += q1.x; v1.y += q1.y;
            }
            *(float2*)&C[o0] = v0;
            *(float2*)&C[o1] = v1;
        }
    }
}

// ================= per-chunk prep =================
#define WKS 68
#define PREP_SMEM ((65*WKS + 4096 + 4096 + 64*3 + 8)*4)

__global__ __launch_bounds__(256) void prep_kernel(const float* __restrict__ x)
{
    extern __shared__ float sm[];
    float* WK    = sm;
    float* Gm    = WK + 65*WKS;
    float* Mb    = Gm + 4096;
    float* cum   = Mb + 4096;
    float* dexpv = cum + 64;
    float* betav = dexpv + 64;

    int cid = blockIdx.x;
    int b = cid / (H_*N_);
    int h = (cid / N_) % H_;
    int n = cid % N_;
    int t = threadIdx.x;
    size_t xbase = ((size_t)b*T_ + (size_t)n*C_)*D_ + (size_t)h*64;
    size_t base  = (size_t)cid*4096;

    for (int f = t; f < 65*16; f += 256){
        int r = f >> 4, j4 = (f & 15)*4;
        float4 v;
        if (r == 0 && n == 0) v = make_float4(0.f,0.f,0.f,0.f);
        else v = *(const float4*)&x[xbase + ((size_t)r-1)*D_ + j4];
        *(float4*)&WK[r*WKS + j4] = v;
    }
    if (t < 64){
        int tok = (b*T_ + n*C_ + t)*H_ + h;
        betav[t] = g_beta[tok];
        cum[t]   = g_dec[tok];
    }
    __syncthreads();

    if (t < 65){
        float s = 0.f;
        #pragma unroll
        for (int q=0;q<16;q++){
            float4 v = *(float4*)&WK[t*WKS + q*4];
            s += v.x*v.x + v.y*v.y + v.z*v.z + v.w*v.w;
        }
        float inv = 1.f/fmaxf(sqrtf(s), 1e-12f);
        #pragma unroll
        for (int q=0;q<16;q++){
            float4 v = *(float4*)&WK[t*WKS + q*4];
            v.x*=inv; v.y*=inv; v.z*=inv; v.w*=inv;
            *(float4*)&WK[t*WKS + q*4] = v;
        }
    }
    if (t == 65){
        float s = 0.f;
        for (int c=0;c<64;c++){ s += cum[c]; cum[c] = s; }
    }
    __syncthreads();
    if (t < 64) dexpv[t] = __expf(cum[t]);

    for (int f = t; f < 1024; f += 256){
        int i = f >> 4, j4 = (f & 15)*4;
        float4 v = *(const float4*)&g_v[xbase + (size_t)i*D_ + j4];
        float bt = betav[i];
        v.x*=bt; v.y*=bt; v.z*=bt; v.w*=bt;
        *(float4*)&Gm[i*64 + j4] = v;
    }
    __syncthreads();

    float y[64];
    if (t < 128){
        if (t < 64){
            #pragma unroll
            for (int i=0;i<64;i++) y[i] = Gm[i*64 + t];
        } else {
            int jj = t - 64;
            #pragma unroll
            for (int i=0;i<64;i++) y[i] = WK[i*WKS + jj]*betav[i]*dexpv[i];
        }
    }
    __syncthreads();

    {
        int tr = (t >> 4)*4, tc = (t & 15)*4;
        float d[4][4];
        #pragma unroll
        for (int a=0;a<4;a++)
            #pragma unroll
            for (int c=0;c<4;c++) d[a][c]=0.f;
        for (int m4=0; m4<64; m4+=4){
            float4 av[4], cv[4];
            #pragma unroll
            for (int a=0;a<4;a++) av[a] = *(float4*)&WK[(tr+a+1)*WKS + m4];
            #pragma unroll
            for (int c=0;c<4;c++) cv[c] = *(float4*)&WK[(tc+c)*WKS + m4];
            #pragma unroll
            for (int a=0;a<4;a++)
                #pragma unroll
                for (int c=0;c<4;c++)
                    d[a][c] += av[a].x*cv[c].x + av[a].y*cv[c].y
                             + av[a].z*cv[c].z + av[a].w*cv[c].w;
        }
        __syncthreads();
        #pragma unroll
        for (int a=0;a<4;a++)
            #pragma unroll
            for (int c=0;c<4;c++)
                Gm[(tr+a)*64 + tc+c] = d[a][c];
    }
    __syncthreads();

    for (int f = t; f < 4096; f += 256){
        int i = f >> 6, j = f & 63;
        Mb[f] = (j < i) ? (-betav[i]*__expf(cum[i]-cum[j])*Gm[(i-1)*64 + j]) : 0.f;
    }
    __syncthreads();

    float cum63 = cum[63];

    if (t < 128){
        #pragma unroll
        for (int k=0;k<63;k++){
            float yk = y[k];
            #pragma unroll
            for (int i=k+1;i<64;i++)
                y[i] = fmaf(Mb[i*64 + k], yk, y[i]);
        }
        if (t < 64){
            #pragma unroll
            for (int i=0;i<64;i++) g_vc[base + i*64 + t] = y[i];
        } else {
            int jj = t - 64;
            #pragma unroll
            for (int i=0;i<64;i++) g_wkcd[base + i*64 + jj] = -y[i];   // NEGATED
        }
    } else {
        int tt = t - 128;
        for (int f = tt; f < 4096; f += 128){
            int i = f >> 6, j = f & 63;
            g_intra[base + f] = (i >= j) ? (__expf(cum[i]-cum[j])*Gm[f]) : 0.f;
        }
        for (int f = tt; f < 1024; f += 128){
            int i = f >> 4, j4 = (f & 15)*4;
            float4 v = *(float4*)&WK[(i+1)*WKS + j4];
            float dv = dexpv[i];
            v.x*=dv; v.y*=dv; v.z*=dv; v.w*=dv;
            *(float4*)&g_rkd[base + i*64 + j4] = v;
        }
        for (int f = tt; f < 4096; f += 128){
            int jt = f >> 6, ct = f & 63;
            g_wkdw[base + f] = WK[ct*WKS + jt]*__expf(cum63 - cum[ct]);
        }
        if (t == 128) g_elast[cid] = __expf(cum63);
    }
}

// ================= scan: cluster of 2, f32x2 packed math =================
#define SS 36
#define TS 68
#define SCAN_SMEM ((3*64*SS + 4*64*TS + 64 + 32)*4)

__global__ __launch_bounds__(256) __cluster_dims__(2,1,1) void scan_kernel()
{
    extern __shared__ float sm[];
    float* S     = sm;
    float* VN    = S + 64*SS;
    float* VC    = VN + 64*SS;
    float* WKCD  = VC + 64*SS;
    float* RKD   = WKCD + 64*TS;
    float* INTRA = RKD + 64*TS;
    float* WKDW  = INTRA + 64*TS;
    float* gatev = WKDW + 64*TS;
    float* misc  = gatev + 64;

    int bid = blockIdx.x;
    int bh = bid >> 1, half = bid & 1;
    int b = bh >> 4, h = bh & 15;
    int t = threadIdx.x;
    int lane = t & 31, w = t >> 5;
    int ebl = (t & 7) * 4;
    int cbl = (t >> 3) * 2;

    uint32_t exch_addr = smem_u32(&misc[10]);
    uint32_t peer = half ^ 1;

    for (int i=t; i<64*SS; i+=256) S[i]=0.f;
    __syncthreads();

    for (int n=0; n<64; n++){
        size_t gb = ((size_t)bh*64 + n)*4096;
        #pragma unroll
        for (int u=0; u<4; u++){
            int q = u*256 + t;
            int c = q >> 4, jv = (q & 15)*4;
            int so = c*TS + jv;
            *(float4*)&WKCD[so]  = *(const float4*)&g_wkcd[gb + c*64 + jv];
            *(float4*)&RKD[so]   = *(const float4*)&g_rkd[gb + c*64 + jv];
            *(float4*)&INTRA[so] = *(const float4*)&g_intra[gb + c*64 + jv];
            *(float4*)&WKDW[so]  = *(const float4*)&g_wkdw[gb + c*64 + jv];
        }
        #pragma unroll
        for (int u=0; u<2; u++){
            int q = u*256 + t;
            int c = q >> 3, jv = (q & 7)*4;
            *(float4*)&VC[c*SS + jv] = *(const float4*)&g_vc[gb + c*64 + half*32 + jv];
        }
        if (t < 64) gatev[t] = g_gate[((size_t)b*T_ + n*64 + t)*H_ + h];
        if (t == 0) misc[8] = g_elast[bh*64 + n];
        __syncthreads();

        // v_new = vc + (-wkcd) @ S   (fma2)
        {
            u64 acc[2][2];
            #pragma unroll
            for (int ci=0;ci<2;ci++){
                u64x2 v = *(u64x2*)&VC[(cbl+ci)*SS + ebl];
                acc[ci][0]=v.a; acc[ci][1]=v.b;
            }
            #pragma unroll 4
            for (int k4=0;k4<64;k4+=4){
                u64x2 s0 = *(u64x2*)&S[(k4+0)*SS + ebl];
                u64x2 s1 = *(u64x2*)&S[(k4+1)*SS + ebl];
                u64x2 s2 = *(u64x2*)&S[(k4+2)*SS + ebl];
                u64x2 s3 = *(u64x2*)&S[(k4+3)*SS + ebl];
                #pragma unroll
                for (int ci=0;ci<2;ci++){
                    float4 wv = *(float4*)&WKCD[(cbl+ci)*TS + k4];
                    u64 w;
                    w = pk2(wv.x); fma2(acc[ci][0], w, s0.a); fma2(acc[ci][1], w, s0.b);
                    w = pk2(wv.y); fma2(acc[ci][0], w, s1.a); fma2(acc[ci][1], w, s1.b);
                    w = pk2(wv.z); fma2(acc[ci][0], w, s2.a); fma2(acc[ci][1], w, s2.b);
                    w = pk2(wv.w); fma2(acc[ci][0], w, s3.a); fma2(acc[ci][1], w, s3.b);
                }
            }
            #pragma unroll
            for (int ci=0;ci<2;ci++){
                u64x2 o; o.a = acc[ci][0]; o.b = acc[ci][1];
                *(u64x2*)&VN[(cbl+ci)*SS + ebl] = o;
            }
        }
        __syncthreads();

        // o = rkd@S + intra@v_new ; upd = wkdw_T @ v_new  (fma2)
        u64 oa[2][2] = {{0ull,0ull},{0ull,0ull}};
        u64 ud[2][2] = {{0ull,0ull},{0ull,0ull}};
        {
            #pragma unroll 4
            for (int k4=0;k4<64;k4+=4){
                u64x2 s0 = *(u64x2*)&S[(k4+0)*SS + ebl];
                u64x2 s1 = *(u64x2*)&S[(k4+1)*SS + ebl];
                u64x2 s2 = *(u64x2*)&S[(k4+2)*SS + ebl];
                u64x2 s3 = *(u64x2*)&S[(k4+3)*SS + ebl];
                #pragma unroll
                for (int ci=0;ci<2;ci++){
                    float4 wv = *(float4*)&RKD[(cbl+ci)*TS + k4];
                    u64 w;
                    w = pk2(wv.x); fma2(oa[ci][0], w, s0.a); fma2(oa[ci][1], w, s0.b);
                    w = pk2(wv.y); fma2(oa[ci][0], w, s1.a); fma2(oa[ci][1], w, s1.b);
                    w = pk2(wv.z); fma2(oa[ci][0], w, s2.a); fma2(oa[ci][1], w, s2.b);
                    w = pk2(wv.w); fma2(oa[ci][0], w, s3.a); fma2(oa[ci][1], w, s3.b);
                }
            }
            #pragma unroll 4
            for (int k4=0;k4<64;k4+=4){
                u64x2 v0 = *(u64x2*)&VN[(k4+0)*SS + ebl];
                u64x2 v1 = *(u64x2*)&VN[(k4+1)*SS + ebl];
                u64x2 v2 = *(u64x2*)&VN[(k4+2)*SS + ebl];
                u64x2 v3 = *(u64x2*)&VN[(k4+3)*SS + ebl];
                #pragma unroll
                for (int ci=0;ci<2;ci++){
                    float4 wv = *(float4*)&INTRA[(cbl+ci)*TS + k4];
                    u64 w;
                    w = pk2(wv.x); fma2(oa[ci][0], w, v0.a); fma2(oa[ci][1], w, v0.b);
                    w = pk2(wv.y); fma2(oa[ci][0], w, v1.a); fma2(oa[ci][1], w, v1.b);
                    w = pk2(wv.z); fma2(oa[ci][0], w, v2.a); fma2(oa[ci][1], w, v2.b);
                    w = pk2(wv.w); fma2(oa[ci][0], w, v3.a); fma2(oa[ci][1], w, v3.b);
                }
                #pragma unroll
                for (int di=0;di<2;di++){
                    float4 wd = *(float4*)&WKDW[(cbl+di)*TS + k4];
                    u64 w;
                    w = pk2(wd.x); fma2(ud[di][0], w, v0.a); fma2(ud[di][1], w, v0.b);
                    w = pk2(wd.y); fma2(ud[di][0], w, v1.a); fma2(ud[di][1], w, v1.b);
                    w = pk2(wd.z); fma2(ud[di][0], w, v2.a); fma2(ud[di][1], w, v2.b);
                    w = pk2(wd.w); fma2(ud[di][0], w, v3.a); fma2(ud[di][1], w, v3.b);
                }
            }
            #pragma unroll
            for (int ci=0;ci<2;ci++){
                float gt = gatev[cbl+ci];
                float2 p0 = up2(oa[ci][0]), p1 = up2(oa[ci][1]);
                __nv_bfloat162 b0 = __floats2bfloat162_rn(p0.x*gt, p0.y*gt);
                __nv_bfloat162 b1 = __floats2bfloat162_rn(p1.x*gt, p1.y*gt);
                size_t orow = ((size_t)b*T_ + n*64 + cbl+ci)*D_ + (size_t)h*64 + half*32 + ebl;
                *(__nv_bfloat162*)&g_ogb[orow]   = b0;
                *(__nv_bfloat162*)&g_ogb[orow+2] = b1;
            }
        }
        __syncthreads();

        // S = S*elast + upd ; partial Frobenius
        float el = misc[8];
        float partial = 0.f;
        #pragma unroll
        for (int di=0;di<2;di++){
            float2 u0 = up2(ud[di][0]), u1 = up2(ud[di][1]);
            float uu[4] = {u0.x, u0.y, u1.x, u1.y};
            #pragma unroll
            for (int ei=0;ei<4;ei++){
                int idx = (cbl+di)*SS + ebl + ei;
                float sv = S[idx]*el + uu[ei];
                S[idx] = sv;
                partial += sv*sv;
            }
        }
        #pragma unroll
        for (int off=16; off>0; off>>=1) partial += __shfl_down_sync(0xffffffffu, partial, off);
        if (lane==0) misc[w] = partial;
        __syncthreads();
        if (t==0){
            float s=0.f;
            #pragma unroll
            for (int i=0;i<8;i++) s += misc[i];
            misc[9] = s;
            uint32_t remote;
            asm volatile("mapa.shared::cluster.u32 %0, %1, %2;" : "=r"(remote)
                         : "r"(exch_addr + (n&1)*4), "r"(peer));
            asm volatile("st.shared::cluster.f32 [%0], %1;" :: "r"(remote), "f"(s) : "memory");
        }
        asm volatile("barrier.cluster.arrive.aligned;" ::: "memory");
        asm volatile("barrier.cluster.wait.aligned;" ::: "memory");
        float total = misc[9] + misc[10 + (n&1)];
        float nrm = sqrtf(total);
        float f = fminf(nrm,100.f)/fmaxf(nrm,1e-6f);
        #pragma unroll
        for (int di=0;di<2;di++)
            #pragma unroll
            for (int ei=0;ei<4;ei++)
                S[(cbl+di)*SS + ebl + ei] *= f;
        __syncthreads();
    }
}

extern "C" void kernel_launch(void* const* d_in, const int* in_sizes, int n_in,
                              void* d_out, int out_size) {
    const float* x      = (const float*)d_in[0];
    const float* w_wr   = (const float*)d_in[1];
    const float* w_gate = (const float*)d_in[2];
    const float* w_out  = (const float*)d_in[3];
    const float* w_beta = (const float*)d_in[4];
    const float* w_alph = (const float*)d_in[5];
    const float* dtb    = (const float*)d_in[6];
    const float* alog   = (const float*)d_in[7];
    float* out = (float*)d_out;

    cudaFuncSetAttribute(proj_kernel, cudaFuncAttributeMaxDynamicSharedMemorySize, PROJ_SMEM);
    cudaFuncSetAttribute(prep_kernel, cudaFuncAttributeMaxDynamicSharedMemorySize, PREP_SMEM);
    cudaFuncSetAttribute(scan_kernel, cudaFuncAttributeMaxDynamicSharedMemorySize, SCAN_SMEM);
    cudaFuncSetAttribute(hgemm,       cudaFuncAttributeMaxDynamicSharedMemorySize, G_SMEM);

    __nv_bfloat16 *xb, *ogb, *wb0, *wb1;
    cudaGetSymbolAddress((void**)&xb,  g_xb);
    cudaGetSymbolAddress((void**)&ogb, g_ogb);
    cudaGetSymbolAddress((void**)&wb0, g_wb0);
    cudaGetSymbolAddress((void**)&wb1, g_wb1);
    float* gv; cudaGetSymbolAddress((void**)&gv, g_v);

    proj_kernel<<<128, 256, PROJ_SMEM>>>(x, w_gate, w_beta, w_alph, dtb, alog);
    cvt_kernel<<<(BT_*D_/4 + 255)/256, 256>>>(x, xb, BT_*D_/4);
    cvt_kernel<<<(D_*D_/4 + 255)/256, 256>>>(w_wr, wb0, D_*D_/4);
    cvt_kernel<<<(D_*D_/4 + 255)/256, 256>>>(w_out, wb1, D_*D_/4);
    hgemm<<<dim3(8,128), 256, G_SMEM>>>(xb, wb0, nullptr, gv, 0);
    prep_kernel<<<BHN_, 256, PREP_SMEM>>>(x);
    scan_kernel<<<128, 256, SCAN_SMEM>>>();
    hgemm<<<dim3(8,128), 256, G_SMEM>>>(ogb, wb1, x, out, 1);
}